// round 1
// baseline (speedup 1.0000x reference)
#include <cuda_runtime.h>
#include <math.h>

#define Bsz 32
#define Tn  512
#define Dn  512
#define En  8
#define Hn  2048

// Scratch for the hidden activations h = relu(x@W1+b1): [B, T, H] fp32 = 134 MB.
// Device global (static) — allowed under the allocation guards.
__device__ float g_h[(size_t)Bsz * Tn * Hn];
__device__ int   g_expert[Bsz];

// ---------------------------------------------------------------------------
// Router: pooled = mean_t x[b,t,:]; logits = pooled@Wp + bp; softmax; argmax.
// One block per utterance, 256 threads.
// ---------------------------------------------------------------------------
__global__ __launch_bounds__(256) void router_kernel(
    const float* __restrict__ x, const float* __restrict__ Wp,
    const float* __restrict__ bp, float* __restrict__ probs_out,
    float* __restrict__ idx_out)
{
    int b = blockIdx.x;
    __shared__ float pooled[Dn];
    __shared__ float logits[En];

    // mean-pool over T: thread handles columns d, d+256
    for (int d = threadIdx.x; d < Dn; d += 256) {
        const float* xb = x + (size_t)b * Tn * Dn + d;
        float s = 0.f;
        #pragma unroll 8
        for (int t = 0; t < Tn; t++) s += xb[(size_t)t * Dn];
        pooled[d] = s * (1.0f / (float)Tn);
    }
    __syncthreads();

    // warp w computes logit w (E=8 warps)
    int w = threadIdx.x >> 5, lane = threadIdx.x & 31;
    if (w < En) {
        float s = 0.f;
        for (int d = lane; d < Dn; d += 32) s += pooled[d] * Wp[(size_t)d * En + w];
        #pragma unroll
        for (int o = 16; o > 0; o >>= 1) s += __shfl_xor_sync(0xffffffffu, s, o);
        if (lane == 0) logits[w] = s + bp[w];
    }
    __syncthreads();

    if (threadIdx.x == 0) {
        float m = logits[0]; int am = 0;
        #pragma unroll
        for (int e = 1; e < En; e++) if (logits[e] > m) { m = logits[e]; am = e; }
        float ex[En], den = 0.f;
        #pragma unroll
        for (int e = 0; e < En; e++) { ex[e] = expf(logits[e] - m); den += ex[e]; }
        float inv = 1.0f / den;
        #pragma unroll
        for (int e = 0; e < En; e++) probs_out[b * En + e] = ex[e] * inv;
        idx_out[b]  = (float)am;
        g_expert[b] = am;
    }
}

// ---------------------------------------------------------------------------
// Batched expert GEMM: C[b] = act(A[b] @ W[e_b] + bias[e_b])
//   A: [B, M, K] (row-major per batch), W: [E, K, N], C: [B, M, N]
// Tile: 64x64, k-chunk 16, 256 threads, 4x4 per thread.
// ---------------------------------------------------------------------------
template <bool RELU>
__global__ __launch_bounds__(256) void ffn_gemm(
    const float* __restrict__ A, const float* __restrict__ W,
    const float* __restrict__ bias, float* __restrict__ C,
    int M, int N, int K,
    long a_bstride, long c_bstride, long w_estride, long bias_estride)
{
    __shared__ float As[16][65];   // +1 pad: conflict-free column stores
    __shared__ float Bs[16][64];

    int b = blockIdx.z;
    int e = g_expert[b];
    const float* Ab    = A    + (size_t)b * a_bstride;
    const float* Wb    = W    + (size_t)e * w_estride;
    const float* biasb = bias + (size_t)e * bias_estride;
    float*       Cb    = C    + (size_t)b * c_bstride;

    int m0 = blockIdx.y * 64, n0 = blockIdx.x * 64;
    int tid = threadIdx.x;
    int tx = tid & 15, ty = tid >> 4;

    float acc[4][4] = {};

    for (int k0 = 0; k0 < K; k0 += 16) {
        // A tile: 64 rows x 16 k  (store transposed into As[k][m])
        #pragma unroll
        for (int i = 0; i < 4; i++) {
            int lin = tid + i * 256;
            int m = lin >> 4, k = lin & 15;
            As[k][m] = Ab[(size_t)(m0 + m) * K + (k0 + k)];
        }
        // B tile: 16 k x 64 cols (coalesced along n)
        #pragma unroll
        for (int i = 0; i < 4; i++) {
            int lin = tid + i * 256;
            int k = lin >> 6, n = lin & 63;
            Bs[k][n] = Wb[(size_t)(k0 + k) * N + (n0 + n)];
        }
        __syncthreads();

        #pragma unroll
        for (int kk = 0; kk < 16; kk++) {
            float av[4], bv[4];
            #pragma unroll
            for (int i = 0; i < 4; i++) av[i] = As[kk][ty + 16 * i];
            #pragma unroll
            for (int j = 0; j < 4; j++) bv[j] = Bs[kk][tx + 16 * j];
            #pragma unroll
            for (int i = 0; i < 4; i++)
                #pragma unroll
                for (int j = 0; j < 4; j++)
                    acc[i][j] = fmaf(av[i], bv[j], acc[i][j]);
        }
        __syncthreads();
    }

    #pragma unroll
    for (int i = 0; i < 4; i++) {
        int m = m0 + ty + 16 * i;
        #pragma unroll
        for (int j = 0; j < 4; j++) {
            int n = n0 + tx + 16 * j;
            float v = acc[i][j] + biasb[n];
            if (RELU) v = fmaxf(v, 0.f);
            Cb[(size_t)m * N + n] = v;
        }
    }
}

// ---------------------------------------------------------------------------
extern "C" void kernel_launch(void* const* d_in, const int* in_sizes, int n_in,
                              void* d_out, int out_size)
{
    const float* x  = (const float*)d_in[0];
    const float* Wp = (const float*)d_in[1];
    const float* bp = (const float*)d_in[2];
    const float* W1 = (const float*)d_in[3];
    const float* b1 = (const float*)d_in[4];
    const float* W2 = (const float*)d_in[5];
    const float* b2 = (const float*)d_in[6];

    float* out   = (float*)d_out;
    float* probs = out + (size_t)Bsz * Tn * Dn;          // [B, E]
    float* idx   = probs + (size_t)Bsz * En;             // [B, 1] as float

    float* h = nullptr;
    cudaGetSymbolAddress((void**)&h, g_h);

    router_kernel<<<Bsz, 256>>>(x, Wp, bp, probs, idx);

    // h = relu(x @ W1[e] + b1[e])  : M=T, N=H, K=D
    dim3 g1(Hn / 64, Tn / 64, Bsz);
    ffn_gemm<true><<<g1, 256>>>(x, W1, b1, h,
                                Tn, Hn, Dn,
                                (long)Tn * Dn, (long)Tn * Hn,
                                (long)Dn * Hn, (long)Hn);

    // out = h @ W2[e] + b2[e]      : M=T, N=D, K=H
    dim3 g2(Dn / 64, Tn / 64, Bsz);
    ffn_gemm<false><<<g2, 256>>>(h, W2, b2, out,
                                 Tn, Dn, Hn,
                                 (long)Tn * Hn, (long)Tn * Dn,
                                 (long)Hn * Dn, (long)Dn);
}

// round 7
// speedup vs baseline: 2.5021x; 2.5021x over previous
#include <cuda_runtime.h>
#include <cuda_bf16.h>
#include <cstdint>
#include <math.h>

#define Bsz 32
#define Tn  512
#define Dn  512
#define En  8
#define Hn  2048

// ---------------- device scratch (static: allocation-guard safe) ----------
__device__ __align__(16) __nv_bfloat16 g_xh[(size_t)Bsz*Tn*Dn];
__device__ __align__(16) __nv_bfloat16 g_xl[(size_t)Bsz*Tn*Dn];
__device__ __align__(16) __nv_bfloat16 g_w1h[(size_t)En*Hn*Dn];   // [E][H][D] (N-major)
__device__ __align__(16) __nv_bfloat16 g_w1l[(size_t)En*Hn*Dn];
__device__ __align__(16) __nv_bfloat16 g_w2h[(size_t)En*Dn*Hn];   // [E][D][H] (N-major)
__device__ __align__(16) __nv_bfloat16 g_w2l[(size_t)En*Dn*Hn];
__device__ __align__(16) __nv_bfloat16 g_hh[(size_t)Bsz*Tn*Hn];
__device__ __align__(16) __nv_bfloat16 g_hl[(size_t)Bsz*Tn*Hn];
__device__ float g_pool[Bsz][8][Dn];
__device__ int   g_expert[Bsz];

// ---------------- small PTX helpers ---------------------------------------
__device__ __forceinline__ uint32_t smem_u32(const void* p) {
    uint32_t a;
    asm("{ .reg .u64 t; cvta.to.shared.u64 t, %1; cvt.u32.u64 %0, t; }" : "=r"(a) : "l"(p));
    return a;
}
__device__ __forceinline__ void cp16(uint32_t dst, const void* src) {
    asm volatile("cp.async.cg.shared.global [%0], [%1], 16;" :: "r"(dst), "l"(__cvta_generic_to_global(src)));
}
#define CP_COMMIT()  asm volatile("cp.async.commit_group;" ::: "memory")
#define CP_WAIT0()   asm volatile("cp.async.wait_group 0;" ::: "memory")
#define CP_WAIT1()   asm volatile("cp.async.wait_group 1;" ::: "memory")

__device__ __forceinline__ void ldmx4(uint32_t* r, uint32_t addr) {
    asm volatile("ldmatrix.sync.aligned.m8n8.x4.shared.b16 {%0,%1,%2,%3}, [%4];"
                 : "=r"(r[0]), "=r"(r[1]), "=r"(r[2]), "=r"(r[3]) : "r"(addr));
}
__device__ __forceinline__ void mma16816(float* c, const uint32_t* a, uint32_t b0, uint32_t b1) {
    asm volatile("mma.sync.aligned.m16n8k16.row.col.f32.bf16.bf16.f32 "
                 "{%0,%1,%2,%3}, {%4,%5,%6,%7}, {%8,%9}, {%0,%1,%2,%3};"
                 : "+f"(c[0]), "+f"(c[1]), "+f"(c[2]), "+f"(c[3])
                 : "r"(a[0]), "r"(a[1]), "r"(a[2]), "r"(a[3]), "r"(b0), "r"(b1));
}

// ---------------- pre-pass: split x to bf16 hi/lo + pooled partials -------
__global__ __launch_bounds__(256) void split_x_pool(const float* __restrict__ x) {
    int b = blockIdx.x, sl = blockIdx.y;
    const float* xb = x + (size_t)b * Tn * Dn + (size_t)sl * 64 * Dn;
    __nv_bfloat16* oh = g_xh + (size_t)b * Tn * Dn + (size_t)sl * 64 * Dn;
    __nv_bfloat16* ol = g_xl + (size_t)b * Tn * Dn + (size_t)sl * 64 * Dn;
    int t = threadIdx.x;
    float a0 = 0.f, a1 = 0.f;
    for (int r = 0; r < 64; r++) {
        float2 v = ((const float2*)(xb + (size_t)r * Dn))[t];
        __nv_bfloat162 h2 = __floats2bfloat162_rn(v.x, v.y);
        float r0 = v.x - __bfloat162float(h2.x);
        float r1 = v.y - __bfloat162float(h2.y);
        __nv_bfloat162 l2 = __floats2bfloat162_rn(r0, r1);
        ((__nv_bfloat162*)(oh + (size_t)r * Dn))[t] = h2;
        ((__nv_bfloat162*)(ol + (size_t)r * Dn))[t] = l2;
        a0 += v.x; a1 += v.y;
    }
    g_pool[b][sl][2 * t]     = a0;
    g_pool[b][sl][2 * t + 1] = a1;
}

// ---------------- router finish: logits, softmax, argmax ------------------
__global__ __launch_bounds__(256) void router_finish(
    const float* __restrict__ Wp, const float* __restrict__ bp,
    float* __restrict__ probs_out, float* __restrict__ idx_out)
{
    int b = blockIdx.x;
    __shared__ float pooled[Dn];
    __shared__ float logits[En];
    for (int d = threadIdx.x; d < Dn; d += 256) {
        float s = 0.f;
        #pragma unroll
        for (int sl = 0; sl < 8; sl++) s += g_pool[b][sl][d];
        pooled[d] = s * (1.0f / (float)Tn);
    }
    __syncthreads();
    int w = threadIdx.x >> 5, lane = threadIdx.x & 31;
    if (w < En) {
        float s = 0.f;
        for (int d = lane; d < Dn; d += 32) s += pooled[d] * Wp[(size_t)d * En + w];
        #pragma unroll
        for (int o = 16; o > 0; o >>= 1) s += __shfl_xor_sync(0xffffffffu, s, o);
        if (lane == 0) logits[w] = s + bp[w];
    }
    __syncthreads();
    if (threadIdx.x == 0) {
        float m = logits[0]; int am = 0;
        #pragma unroll
        for (int e = 1; e < En; e++) if (logits[e] > m) { m = logits[e]; am = e; }
        float ex[En], den = 0.f;
        #pragma unroll
        for (int e = 0; e < En; e++) { ex[e] = expf(logits[e] - m); den += ex[e]; }
        float inv = 1.0f / den;
        #pragma unroll
        for (int e = 0; e < En; e++) probs_out[b * En + e] = ex[e] * inv;
        idx_out[b]  = (float)am;
        g_expert[b] = am;
    }
}

// ---------------- pre-pass: transpose + split W ---------------------------
// in: [E][R][C]  ->  oh/ol: [E][C][R]
__global__ __launch_bounds__(256) void transpose_split(
    const float* __restrict__ in, __nv_bfloat16* __restrict__ oh,
    __nv_bfloat16* __restrict__ ol, int R, int C)
{
    __shared__ float tile[32][33];
    int e = blockIdx.z;
    int c0 = blockIdx.x * 32, r0 = blockIdx.y * 32;
    const float* ine = in + (size_t)e * R * C;
    int tx = threadIdx.x & 31, ty = threadIdx.x >> 5;   // ty: 0..7
    #pragma unroll
    for (int i = 0; i < 32; i += 8)
        tile[ty + i][tx] = ine[(size_t)(r0 + ty + i) * C + (c0 + tx)];
    __syncthreads();
    size_t ob = (size_t)e * R * C;
    #pragma unroll
    for (int i = 0; i < 32; i += 8) {
        int oc = c0 + ty + i;
        float v = tile[tx][ty + i];
        __nv_bfloat16 h = __float2bfloat16(v);
        float resid = v - __bfloat162float(h);
        oh[ob + (size_t)oc * R + r0 + tx] = h;
        ol[ob + (size_t)oc * R + r0 + tx] = __float2bfloat16(resid);
    }
}

// ---------------- HMMA GEMM ------------------------------------------------
// C[b](M, Ntot) = act(A[b](M,K) @ Bt[e](Ntot,K)^T + bias[e]), 3-term hi/lo.
// CTA tile 128x256, 8 warps 2(m)x4(n), warp tile 64x64. k-chunk = 32.
#define MT 128
#define NT 256
#define KC 32
#define ASTRIDE 80                    // bytes per smem row (32 bf16 + 16B pad)
#define ATILE  (MT * ASTRIDE)         // 10240
#define BTILE  (NT * ASTRIDE)         // 20480
#define STAGE  (ATILE + BTILE)        // 30720
#define SMEM_TOTAL (2 * STAGE)        // 61440

__device__ __forceinline__ void load_chunk(
    uint32_t stageBase, const __nv_bfloat16* __restrict__ Asrc,
    const __nv_bfloat16* __restrict__ Bsrc, int K, int k0, int tid)
{
    // A: 128 rows x 32 cols = 512 x 16B
    #pragma unroll
    for (int it = 0; it < 2; it++) {
        int idx = tid + it * 256;
        int row = idx >> 2, seg = idx & 3;
        cp16(stageBase + row * ASTRIDE + seg * 16,
             Asrc + (size_t)row * K + k0 + seg * 8);
    }
    // B: 256 rows x 32 cols = 1024 x 16B
    #pragma unroll
    for (int it = 0; it < 4; it++) {
        int idx = tid + it * 256;
        int row = idx >> 2, seg = idx & 3;
        cp16(stageBase + ATILE + row * ASTRIDE + seg * 16,
             Bsrc + (size_t)row * K + k0 + seg * 8);
    }
}

template <bool FUSE1>
__global__ __launch_bounds__(256, 1) void mma_gemm(
    const __nv_bfloat16* __restrict__ Ah, const __nv_bfloat16* __restrict__ Al,
    const __nv_bfloat16* __restrict__ Bh, const __nv_bfloat16* __restrict__ Bl,
    const float* __restrict__ bias,
    __nv_bfloat16* __restrict__ out_h, __nv_bfloat16* __restrict__ out_l,
    float* __restrict__ out_f, int K, int Ntot)
{
    extern __shared__ char smem[];
    uint32_t sb = smem_u32(smem);
    int tid = threadIdx.x, wid = tid >> 5, lane = tid & 31;
    int warp_m = wid & 1, warp_n = wid >> 1;
    int b = blockIdx.z, e = g_expert[b];
    int m0 = blockIdx.y * MT, n0 = blockIdx.x * NT;

    const __nv_bfloat16* Abh = Ah + (size_t)b * Tn * K + (size_t)m0 * K;
    const __nv_bfloat16* Abl = Al + (size_t)b * Tn * K + (size_t)m0 * K;
    const __nv_bfloat16* Bbh = Bh + (size_t)e * Ntot * K + (size_t)n0 * K;
    const __nv_bfloat16* Bbl = Bl + (size_t)e * Ntot * K + (size_t)n0 * K;

    const int kper = K / KC;          // chunks per term
    const int nc = 3 * kper;          // slots: (Ah,Bh), (Ah,Bl), (Al,Bh)

    float acc[4][8][4];
    #pragma unroll
    for (int i = 0; i < 4; i++)
        #pragma unroll
        for (int j = 0; j < 8; j++)
            #pragma unroll
            for (int q = 0; q < 4; q++) acc[i][j][q] = 0.f;

    // prologue: chunks 0, 1
    #pragma unroll 1
    for (int p = 0; p < 2; p++) {
        int slot = p / kper, kk = p % kper;
        const __nv_bfloat16* As = (slot < 2) ? Abh : Abl;
        const __nv_bfloat16* Bs = (slot == 1) ? Bbl : Bbh;
        load_chunk(sb + p * STAGE, As, Bs, K, kk * KC, tid);
        CP_COMMIT();
    }

    // per-lane ldmatrix base offsets (within a stage)
    uint32_t lm_row = (lane & 15), lm_half = (lane >> 4) << 4;   // 16B half select
    uint32_t aoff = lm_row * ASTRIDE + lm_half + (warp_m * 64) * ASTRIDE;
    uint32_t boff = ATILE + lm_row * ASTRIDE + lm_half + (warp_n * 64) * ASTRIDE;

    for (int i = 0; i < nc; i++) {
        int s = i & 1;
        if (i == nc - 1) CP_WAIT0(); else CP_WAIT1();
        __syncthreads();

        uint32_t stg = sb + s * STAGE;
        #pragma unroll
        for (int ks = 0; ks < 2; ks++) {
            uint32_t a[4][4], bq[4][4];
            #pragma unroll
            for (int ia = 0; ia < 4; ia++)
                ldmx4(a[ia], stg + aoff + ia * 16 * ASTRIDE + ks * 32);
            #pragma unroll
            for (int jp = 0; jp < 4; jp++)
                ldmx4(bq[jp], stg + boff + jp * 16 * ASTRIDE + ks * 32);
            #pragma unroll
            for (int ia = 0; ia < 4; ia++)
                #pragma unroll
                for (int j = 0; j < 8; j++) {
                    int jp = j >> 1, hi = j & 1;
                    mma16816(acc[ia][j], a[ia], bq[jp][hi], bq[jp][hi + 2]);
                }
        }
        __syncthreads();

        int p = i + 2;
        if (p < nc) {
            int slot = p / kper, kk = p % kper;
            const __nv_bfloat16* As = (slot < 2) ? Abh : Abl;
            const __nv_bfloat16* Bs = (slot == 1) ? Bbl : Bbh;
            load_chunk(sb + s * STAGE, As, Bs, K, kk * KC, tid);
            CP_COMMIT();
        }
    }

    // ------------- epilogue -------------
    int mrow = m0 + warp_m * 64 + (lane >> 2);
    int ncol = n0 + warp_n * 64 + (lane & 3) * 2;
    const float* bb = bias + (size_t)e * Ntot;

    #pragma unroll
    for (int ia = 0; ia < 4; ia++) {
        #pragma unroll
        for (int j = 0; j < 8; j++) {
            int n = ncol + j * 8;
            float2 b2 = *(const float2*)(bb + n);
            #pragma unroll
            for (int half = 0; half < 2; half++) {
                int m = mrow + ia * 16 + half * 8;
                float v0 = acc[ia][j][2 * half]     + b2.x;
                float v1 = acc[ia][j][2 * half + 1] + b2.y;
                if (FUSE1) {
                    v0 = fmaxf(v0, 0.f); v1 = fmaxf(v1, 0.f);
                    __nv_bfloat162 h2 = __floats2bfloat162_rn(v0, v1);
                    float r0 = v0 - __bfloat162float(h2.x);
                    float r1 = v1 - __bfloat162float(h2.y);
                    __nv_bfloat162 l2 = __floats2bfloat162_rn(r0, r1);
                    *(__nv_bfloat162*)(out_h + ((size_t)b * Tn + m) * Ntot + n) = h2;
                    *(__nv_bfloat162*)(out_l + ((size_t)b * Tn + m) * Ntot + n) = l2;
                } else {
                    float2 o = make_float2(v0, v1);
                    *(float2*)(out_f + ((size_t)b * Tn + m) * Ntot + n) = o;
                }
            }
        }
    }
}

// ---------------------------------------------------------------------------
extern "C" void kernel_launch(void* const* d_in, const int* in_sizes, int n_in,
                              void* d_out, int out_size)
{
    const float* x  = (const float*)d_in[0];
    const float* Wp = (const float*)d_in[1];
    const float* bp = (const float*)d_in[2];
    const float* W1 = (const float*)d_in[3];
    const float* b1 = (const float*)d_in[4];
    const float* W2 = (const float*)d_in[5];
    const float* b2 = (const float*)d_in[6];

    float* out   = (float*)d_out;
    float* probs = out + (size_t)Bsz * Tn * Dn;
    float* idx   = probs + (size_t)Bsz * En;

    __nv_bfloat16 *xh, *xl, *w1h, *w1l, *w2h, *w2l, *hh, *hl;
    cudaGetSymbolAddress((void**)&xh,  g_xh);
    cudaGetSymbolAddress((void**)&xl,  g_xl);
    cudaGetSymbolAddress((void**)&w1h, g_w1h);
    cudaGetSymbolAddress((void**)&w1l, g_w1l);
    cudaGetSymbolAddress((void**)&w2h, g_w2h);
    cudaGetSymbolAddress((void**)&w2l, g_w2l);
    cudaGetSymbolAddress((void**)&hh,  g_hh);
    cudaGetSymbolAddress((void**)&hl,  g_hl);

    cudaFuncSetAttribute(mma_gemm<true>,  cudaFuncAttributeMaxDynamicSharedMemorySize, SMEM_TOTAL);
    cudaFuncSetAttribute(mma_gemm<false>, cudaFuncAttributeMaxDynamicSharedMemorySize, SMEM_TOTAL);

    split_x_pool<<<dim3(Bsz, 8), 256>>>(x);
    router_finish<<<Bsz, 256>>>(Wp, bp, probs, idx);
    transpose_split<<<dim3(Hn / 32, Dn / 32, En), 256>>>(W1, w1h, w1l, Dn, Hn);
    transpose_split<<<dim3(Dn / 32, Hn / 32, En), 256>>>(W2, w2h, w2l, Hn, Dn);

    // GEMM1: h = relu(x @ W1[e] + b1[e]),  K=D, Ntot=H
    mma_gemm<true><<<dim3(Hn / NT, Tn / MT, Bsz), 256, SMEM_TOTAL>>>(
        xh, xl, w1h, w1l, b1, hh, hl, nullptr, Dn, Hn);
    // GEMM2: out = h @ W2[e] + b2[e],      K=H, Ntot=D
    mma_gemm<false><<<dim3(Dn / NT, Tn / MT, Bsz), 256, SMEM_TOTAL>>>(
        hh, hl, w2h, w2l, b2, nullptr, nullptr, out, Hn, Dn);
}

// round 8
// speedup vs baseline: 2.9670x; 1.1858x over previous
#include <cuda_runtime.h>
#include <cuda_bf16.h>
#include <cstdint>
#include <math.h>

#define Bsz 32
#define Tn  512
#define Dn  512
#define En  8
#define Hn  2048

// ---------------- device scratch (static: allocation-guard safe) ----------
__device__ __align__(16) __nv_bfloat16 g_xh[(size_t)Bsz*Tn*Dn];
__device__ __align__(16) __nv_bfloat16 g_xl[(size_t)Bsz*Tn*Dn];
__device__ __align__(16) __nv_bfloat16 g_w1h[(size_t)En*Hn*Dn];   // [E][H][D] (N-major)
__device__ __align__(16) __nv_bfloat16 g_w1l[(size_t)En*Hn*Dn];
__device__ __align__(16) __nv_bfloat16 g_w2h[(size_t)En*Dn*Hn];   // [E][D][H] (N-major)
__device__ __align__(16) __nv_bfloat16 g_w2l[(size_t)En*Dn*Hn];
__device__ __align__(16) __nv_bfloat16 g_hh[(size_t)Bsz*Tn*Hn];
__device__ __align__(16) __nv_bfloat16 g_hl[(size_t)Bsz*Tn*Hn];
__device__ float g_pool[Bsz][8][Dn];
__device__ int   g_expert[Bsz];

// ---------------- small PTX helpers ---------------------------------------
__device__ __forceinline__ uint32_t smem_u32(const void* p) {
    uint32_t a;
    asm("{ .reg .u64 t; cvta.to.shared.u64 t, %1; cvt.u32.u64 %0, t; }" : "=r"(a) : "l"(p));
    return a;
}
__device__ __forceinline__ void cp16(uint32_t dst, const void* src) {
    asm volatile("cp.async.cg.shared.global [%0], [%1], 16;" :: "r"(dst), "l"(__cvta_generic_to_global(src)));
}
#define CP_COMMIT()  asm volatile("cp.async.commit_group;" ::: "memory")
#define CP_WAIT2()   asm volatile("cp.async.wait_group 2;" ::: "memory")

__device__ __forceinline__ void ldmx4(uint32_t* r, uint32_t addr) {
    asm volatile("ldmatrix.sync.aligned.m8n8.x4.shared.b16 {%0,%1,%2,%3}, [%4];"
                 : "=r"(r[0]), "=r"(r[1]), "=r"(r[2]), "=r"(r[3]) : "r"(addr));
}
__device__ __forceinline__ void mma16816(float* c, const uint32_t* a, uint32_t b0, uint32_t b1) {
    asm volatile("mma.sync.aligned.m16n8k16.row.col.f32.bf16.bf16.f32 "
                 "{%0,%1,%2,%3}, {%4,%5,%6,%7}, {%8,%9}, {%0,%1,%2,%3};"
                 : "+f"(c[0]), "+f"(c[1]), "+f"(c[2]), "+f"(c[3])
                 : "r"(a[0]), "r"(a[1]), "r"(a[2]), "r"(a[3]), "r"(b0), "r"(b1));
}

// ---------------- pre-pass: split x to bf16 hi/lo + pooled partials -------
__global__ __launch_bounds__(256) void split_x_pool(const float* __restrict__ x) {
    int b = blockIdx.x, sl = blockIdx.y;
    const float* xb = x + (size_t)b * Tn * Dn + (size_t)sl * 64 * Dn;
    __nv_bfloat16* oh = g_xh + (size_t)b * Tn * Dn + (size_t)sl * 64 * Dn;
    __nv_bfloat16* ol = g_xl + (size_t)b * Tn * Dn + (size_t)sl * 64 * Dn;
    int t = threadIdx.x;
    float a0 = 0.f, a1 = 0.f;
    for (int r = 0; r < 64; r++) {
        float2 v = ((const float2*)(xb + (size_t)r * Dn))[t];
        __nv_bfloat162 h2 = __floats2bfloat162_rn(v.x, v.y);
        float r0 = v.x - __bfloat162float(h2.x);
        float r1 = v.y - __bfloat162float(h2.y);
        __nv_bfloat162 l2 = __floats2bfloat162_rn(r0, r1);
        ((__nv_bfloat162*)(oh + (size_t)r * Dn))[t] = h2;
        ((__nv_bfloat162*)(ol + (size_t)r * Dn))[t] = l2;
        a0 += v.x; a1 += v.y;
    }
    g_pool[b][sl][2 * t]     = a0;
    g_pool[b][sl][2 * t + 1] = a1;
}

// ---------------- router finish: logits, softmax, argmax ------------------
__global__ __launch_bounds__(256) void router_finish(
    const float* __restrict__ Wp, const float* __restrict__ bp,
    float* __restrict__ probs_out, float* __restrict__ idx_out)
{
    int b = blockIdx.x;
    __shared__ float pooled[Dn];
    __shared__ float logits[En];
    for (int d = threadIdx.x; d < Dn; d += 256) {
        float s = 0.f;
        #pragma unroll
        for (int sl = 0; sl < 8; sl++) s += g_pool[b][sl][d];
        pooled[d] = s * (1.0f / (float)Tn);
    }
    __syncthreads();
    int w = threadIdx.x >> 5, lane = threadIdx.x & 31;
    if (w < En) {
        float s = 0.f;
        for (int d = lane; d < Dn; d += 32) s += pooled[d] * Wp[(size_t)d * En + w];
        #pragma unroll
        for (int o = 16; o > 0; o >>= 1) s += __shfl_xor_sync(0xffffffffu, s, o);
        if (lane == 0) logits[w] = s + bp[w];
    }
    __syncthreads();
    if (threadIdx.x == 0) {
        float m = logits[0]; int am = 0;
        #pragma unroll
        for (int e = 1; e < En; e++) if (logits[e] > m) { m = logits[e]; am = e; }
        float ex[En], den = 0.f;
        #pragma unroll
        for (int e = 0; e < En; e++) { ex[e] = expf(logits[e] - m); den += ex[e]; }
        float inv = 1.0f / den;
        #pragma unroll
        for (int e = 0; e < En; e++) probs_out[b * En + e] = ex[e] * inv;
        idx_out[b]  = (float)am;
        g_expert[b] = am;
    }
}

// ---------------- pre-pass: transpose + split W1 and W2 (one launch) ------
// z in [0,8): W1 [E][Dn][Hn] -> [E][Hn][Dn];  z in [8,16): W2 [E][Hn][Dn] -> [E][Dn][Hn]
__global__ __launch_bounds__(256) void transpose_split_all(
    const float* __restrict__ W1, const float* __restrict__ W2)
{
    __shared__ float tile[32][33];
    bool isW1 = blockIdx.z < En;
    int e = isW1 ? blockIdx.z : blockIdx.z - En;
    int R = isW1 ? Dn : Hn;
    int C = isW1 ? Hn : Dn;
    int c0 = (isW1 ? blockIdx.x : blockIdx.y) * 32;
    int r0 = (isW1 ? blockIdx.y : blockIdx.x) * 32;
    const float* in = (isW1 ? W1 : W2) + (size_t)e * R * C;
    __nv_bfloat16* oh = (isW1 ? g_w1h : g_w2h);
    __nv_bfloat16* ol = (isW1 ? g_w1l : g_w2l);
    int tx = threadIdx.x & 31, ty = threadIdx.x >> 5;
    #pragma unroll
    for (int i = 0; i < 32; i += 8)
        tile[ty + i][tx] = in[(size_t)(r0 + ty + i) * C + (c0 + tx)];
    __syncthreads();
    size_t ob = (size_t)e * R * C;
    #pragma unroll
    for (int i = 0; i < 32; i += 8) {
        int oc = c0 + ty + i;
        float v = tile[tx][ty + i];
        __nv_bfloat16 h = __float2bfloat16(v);
        float resid = v - __bfloat162float(h);
        oh[ob + (size_t)oc * R + r0 + tx] = h;
        ol[ob + (size_t)oc * R + r0 + tx] = __float2bfloat16(resid);
    }
}

// ---------------- HMMA GEMM ------------------------------------------------
// C[b](M, Ntot) = act(A[b](M,K) @ Bt[e](Ntot,K)^T + bias[e]), 3-term hi/lo.
// Combined k-chunk: load Ah/Al/Bh/Bl once, 3 MMA term passes.
// 8 warps arranged WGM x (8/WGM); warp tile 64 x (NT_/(8/WGM)). k-chunk 32.
#define KC 32
#define ASTRIDE 80                    // bytes per smem row (32 bf16 + 16B pad)

template <int MT_, int NT_>
__device__ __forceinline__ void load_chunk2(
    uint32_t stageBase,
    const __nv_bfloat16* __restrict__ Ah, const __nv_bfloat16* __restrict__ Al,
    const __nv_bfloat16* __restrict__ Bh, const __nv_bfloat16* __restrict__ Bl,
    int K, int k0, int tid)
{
    constexpr int ASEGS = MT_ * 4;          // 16B segments per A tile
    #pragma unroll
    for (int idx = tid; idx < 2 * ASEGS; idx += 256) {
        int tl = idx / ASEGS;
        int rem = idx - tl * ASEGS;
        int r = rem >> 2, seg = rem & 3;
        const __nv_bfloat16* src = (tl ? Al : Ah) + (size_t)r * K + k0 + seg * 8;
        cp16(stageBase + tl * MT_ * ASTRIDE + r * ASTRIDE + seg * 16, src);
    }
    constexpr int BSEGS = NT_ * 4;
    uint32_t bbase = stageBase + 2 * MT_ * ASTRIDE;
    #pragma unroll
    for (int idx = tid; idx < 2 * BSEGS; idx += 256) {
        int tl = idx / BSEGS;
        int rem = idx - tl * BSEGS;
        int r = rem >> 2, seg = rem & 3;
        const __nv_bfloat16* src = (tl ? Bl : Bh) + (size_t)r * K + k0 + seg * 8;
        cp16(bbase + tl * NT_ * ASTRIDE + r * ASTRIDE + seg * 16, src);
    }
}

template <int MT_, int NT_, int WGM, bool FUSE1>
__global__ __launch_bounds__(256) void mma_gemm(
    const __nv_bfloat16* __restrict__ Ah, const __nv_bfloat16* __restrict__ Al,
    const __nv_bfloat16* __restrict__ Bh, const __nv_bfloat16* __restrict__ Bl,
    const float* __restrict__ bias,
    __nv_bfloat16* __restrict__ out_h, __nv_bfloat16* __restrict__ out_l,
    float* __restrict__ out_f, int K, int Ntot)
{
    constexpr int WGN   = 8 / WGM;
    constexpr int WCOLS = NT_ / WGN;        // cols per warp
    constexpr int NJP   = WCOLS / 16;       // b ldmatrix.x4 per ks
    constexpr int STAGE_ = (2 * MT_ + 2 * NT_) * ASTRIDE;

    extern __shared__ char smem[];
    uint32_t sb = smem_u32(smem);
    int tid = threadIdx.x, wid = tid >> 5, lane = tid & 31;
    int warp_m = wid % WGM, warp_n = wid / WGM;
    int b = blockIdx.z, e = g_expert[b];
    int m0 = blockIdx.y * MT_, n0 = blockIdx.x * NT_;

    const __nv_bfloat16* Abh = Ah + (size_t)b * Tn * K + (size_t)m0 * K;
    const __nv_bfloat16* Abl = Al + (size_t)b * Tn * K + (size_t)m0 * K;
    const __nv_bfloat16* Bbh = Bh + (size_t)e * Ntot * K + (size_t)n0 * K;
    const __nv_bfloat16* Bbl = Bl + (size_t)e * Ntot * K + (size_t)n0 * K;

    const int nc = K / KC;

    float acc[4][2 * NJP][4];
    #pragma unroll
    for (int i = 0; i < 4; i++)
        #pragma unroll
        for (int j = 0; j < 2 * NJP; j++)
            #pragma unroll
            for (int q = 0; q < 4; q++) acc[i][j][q] = 0.f;

    load_chunk2<MT_, NT_>(sb,          Abh, Abl, Bbh, Bbl, K, 0,  tid); CP_COMMIT();
    load_chunk2<MT_, NT_>(sb + STAGE_, Abh, Abl, Bbh, Bbl, K, KC, tid); CP_COMMIT();

    uint32_t lm_row = (lane & 15), lm_half = (lane >> 4) << 4;
    uint32_t aoff = lm_row * ASTRIDE + lm_half + (warp_m * 64) * ASTRIDE;
    uint32_t boff = 2 * MT_ * ASTRIDE + lm_row * ASTRIDE + lm_half + (warp_n * WCOLS) * ASTRIDE;

    for (int i = 0; i < nc; i++) {
        __syncthreads();                       // all warps done reading stage (i-1)%3
        if (i + 2 < nc)
            load_chunk2<MT_, NT_>(sb + ((i + 2) % 3) * STAGE_, Abh, Abl, Bbh, Bbl,
                                  K, (i + 2) * KC, tid);
        CP_COMMIT();
        CP_WAIT2();                            // chunk i arrived (i+1, i+2 may fly)
        __syncthreads();

        uint32_t stg = sb + (i % 3) * STAGE_;
        #pragma unroll
        for (int p = 0; p < 3; p++) {          // (Ah,Bh), (Ah,Bl), (Al,Bh)
            uint32_t ao = stg + aoff + (p == 2 ? MT_ * ASTRIDE : 0);
            uint32_t bo = stg + boff + (p == 1 ? NT_ * ASTRIDE : 0);
            #pragma unroll
            for (int ks = 0; ks < 2; ks++) {
                uint32_t a[4][4], bq[NJP][4];
                #pragma unroll
                for (int ia = 0; ia < 4; ia++)
                    ldmx4(a[ia], ao + ia * 16 * ASTRIDE + ks * 32);
                #pragma unroll
                for (int jp = 0; jp < NJP; jp++)
                    ldmx4(bq[jp], bo + jp * 16 * ASTRIDE + ks * 32);
                #pragma unroll
                for (int ia = 0; ia < 4; ia++)
                    #pragma unroll
                    for (int j = 0; j < 2 * NJP; j++) {
                        int jp = j >> 1, hi = j & 1;
                        mma16816(acc[ia][j], a[ia], bq[jp][hi], bq[jp][hi + 2]);
                    }
            }
        }
    }

    // ------------- epilogue -------------
    int mrow = m0 + warp_m * 64 + (lane >> 2);
    int ncol = n0 + warp_n * WCOLS + (lane & 3) * 2;
    const float* bb = bias + (size_t)e * Ntot;

    #pragma unroll
    for (int ia = 0; ia < 4; ia++) {
        #pragma unroll
        for (int j = 0; j < 2 * NJP; j++) {
            int n = ncol + j * 8;
            float2 b2 = *(const float2*)(bb + n);
            #pragma unroll
            for (int half = 0; half < 2; half++) {
                int m = mrow + ia * 16 + half * 8;
                float v0 = acc[ia][j][2 * half]     + b2.x;
                float v1 = acc[ia][j][2 * half + 1] + b2.y;
                if (FUSE1) {
                    v0 = fmaxf(v0, 0.f); v1 = fmaxf(v1, 0.f);
                    __nv_bfloat162 h2 = __floats2bfloat162_rn(v0, v1);
                    float r0 = v0 - __bfloat162float(h2.x);
                    float r1 = v1 - __bfloat162float(h2.y);
                    __nv_bfloat162 l2 = __floats2bfloat162_rn(r0, r1);
                    *(__nv_bfloat162*)(out_h + ((size_t)b * Tn + m) * Ntot + n) = h2;
                    *(__nv_bfloat162*)(out_l + ((size_t)b * Tn + m) * Ntot + n) = l2;
                } else {
                    float2 o = make_float2(v0, v1);
                    *(float2*)(out_f + ((size_t)b * Tn + m) * Ntot + n) = o;
                }
            }
        }
    }
}

// ---------------------------------------------------------------------------
extern "C" void kernel_launch(void* const* d_in, const int* in_sizes, int n_in,
                              void* d_out, int out_size)
{
    const float* x  = (const float*)d_in[0];
    const float* Wp = (const float*)d_in[1];
    const float* bp = (const float*)d_in[2];
    const float* W1 = (const float*)d_in[3];
    const float* b1 = (const float*)d_in[4];
    const float* W2 = (const float*)d_in[5];
    const float* b2 = (const float*)d_in[6];

    float* out   = (float*)d_out;
    float* probs = out + (size_t)Bsz * Tn * Dn;
    float* idx   = probs + (size_t)Bsz * En;

    __nv_bfloat16 *xh, *xl, *w1h, *w1l, *w2h, *w2l, *hh, *hl;
    cudaGetSymbolAddress((void**)&xh,  g_xh);
    cudaGetSymbolAddress((void**)&xl,  g_xl);
    cudaGetSymbolAddress((void**)&w1h, g_w1h);
    cudaGetSymbolAddress((void**)&w1l, g_w1l);
    cudaGetSymbolAddress((void**)&w2h, g_w2h);
    cudaGetSymbolAddress((void**)&w2l, g_w2l);
    cudaGetSymbolAddress((void**)&hh,  g_hh);
    cudaGetSymbolAddress((void**)&hl,  g_hl);

    // GEMM1: 128x256 tiles, warps 2x4. GEMM2: 64x128 tiles, warps 1x8.
    constexpr int SMEM1 = 3 * (2 * 128 + 2 * 256) * ASTRIDE;   // 184320
    constexpr int SMEM2 = 3 * (2 * 64 + 2 * 128) * ASTRIDE;    // 92160
    cudaFuncSetAttribute((const void*)mma_gemm<128, 256, 2, true>,
                         cudaFuncAttributeMaxDynamicSharedMemorySize, SMEM1);
    cudaFuncSetAttribute((const void*)mma_gemm<64, 128, 1, false>,
                         cudaFuncAttributeMaxDynamicSharedMemorySize, SMEM2);

    split_x_pool<<<dim3(Bsz, 8), 256>>>(x);
    router_finish<<<Bsz, 256>>>(Wp, bp, probs, idx);
    transpose_split_all<<<dim3(Hn / 32, Dn / 32, 2 * En), 256>>>(W1, W2);

    // GEMM1: h = relu(x @ W1[e] + b1[e]),  K=D, Ntot=H  -> 8x4x32 = 1024 CTAs
    mma_gemm<128, 256, 2, true><<<dim3(Hn / 256, Tn / 128, Bsz), 256, SMEM1>>>(
        xh, xl, w1h, w1l, b1, hh, hl, nullptr, Dn, Hn);
    // GEMM2: out = h @ W2[e] + b2[e],      K=H, Ntot=D  -> 4x8x32 = 1024 CTAs
    mma_gemm<64, 128, 1, false><<<dim3(Dn / 128, Tn / 64, Bsz), 256, SMEM2>>>(
        hh, hl, w2h, w2l, b2, nullptr, nullptr, out, Hn, Dn);
}

// round 10
// speedup vs baseline: 3.1179x; 1.0509x over previous
#include <cuda_runtime.h>
#include <cuda_bf16.h>
#include <cstdint>
#include <math.h>

#define Bsz 32
#define Tn  512
#define Dn  512
#define En  8
#define Hn  2048

// ---------------- device scratch (static: allocation-guard safe) ----------
__device__ __align__(16) __nv_bfloat16 g_xh[(size_t)Bsz*Tn*Dn];
__device__ __align__(16) __nv_bfloat16 g_xl[(size_t)Bsz*Tn*Dn];
__device__ __align__(16) __nv_bfloat16 g_w1h[(size_t)En*Hn*Dn];   // [E][H][D] (N-major)
__device__ __align__(16) __nv_bfloat16 g_w1l[(size_t)En*Hn*Dn];
__device__ __align__(16) __nv_bfloat16 g_w2h[(size_t)En*Dn*Hn];   // [E][D][H] (N-major)
__device__ __align__(16) __nv_bfloat16 g_w2l[(size_t)En*Dn*Hn];
__device__ __align__(16) __nv_bfloat16 g_hh[(size_t)Bsz*Tn*Hn];
__device__ __align__(16) __nv_bfloat16 g_hl[(size_t)Bsz*Tn*Hn];
__device__ float g_pool[Bsz][8][Dn];
__device__ int   g_expert[Bsz];

// ---------------- small PTX helpers ---------------------------------------
__device__ __forceinline__ uint32_t smem_u32(const void* p) {
    uint32_t a;
    asm("{ .reg .u64 t; cvta.to.shared.u64 t, %1; cvt.u32.u64 %0, t; }" : "=r"(a) : "l"(p));
    return a;
}
__device__ __forceinline__ void cp16(uint32_t dst, const void* src) {
    asm volatile("cp.async.cg.shared.global [%0], [%1], 16;" :: "r"(dst), "l"(__cvta_generic_to_global(src)));
}
#define CP_COMMIT()  asm volatile("cp.async.commit_group;" ::: "memory")
#define CP_WAIT0()   asm volatile("cp.async.wait_group 0;" ::: "memory")
#define CP_WAIT1()   asm volatile("cp.async.wait_group 1;" ::: "memory")

__device__ __forceinline__ void ldmx4(uint32_t* r, uint32_t addr) {
    asm volatile("ldmatrix.sync.aligned.m8n8.x4.shared.b16 {%0,%1,%2,%3}, [%4];"
                 : "=r"(r[0]), "=r"(r[1]), "=r"(r[2]), "=r"(r[3]) : "r"(addr));
}
__device__ __forceinline__ void mma16816(float* c, const uint32_t* a, uint32_t b0, uint32_t b1) {
    asm volatile("mma.sync.aligned.m16n8k16.row.col.f32.bf16.bf16.f32 "
                 "{%0,%1,%2,%3}, {%4,%5,%6,%7}, {%8,%9}, {%0,%1,%2,%3};"
                 : "+f"(c[0]), "+f"(c[1]), "+f"(c[2]), "+f"(c[3])
                 : "r"(a[0]), "r"(a[1]), "r"(a[2]), "r"(a[3]), "r"(b0), "r"(b1));
}

// ---------------- pre-pass: split x to bf16 hi/lo + pooled partials -------
__global__ __launch_bounds__(256) void split_x_pool(const float* __restrict__ x) {
    int b = blockIdx.x, sl = blockIdx.y;
    const float* xb = x + (size_t)b * Tn * Dn + (size_t)sl * 64 * Dn;
    __nv_bfloat16* oh = g_xh + (size_t)b * Tn * Dn + (size_t)sl * 64 * Dn;
    __nv_bfloat16* ol = g_xl + (size_t)b * Tn * Dn + (size_t)sl * 64 * Dn;
    int t = threadIdx.x;
    float a0 = 0.f, a1 = 0.f;
    for (int r = 0; r < 64; r++) {
        float2 v = ((const float2*)(xb + (size_t)r * Dn))[t];
        __nv_bfloat162 h2 = __floats2bfloat162_rn(v.x, v.y);
        float r0 = v.x - __bfloat162float(h2.x);
        float r1 = v.y - __bfloat162float(h2.y);
        __nv_bfloat162 l2 = __floats2bfloat162_rn(r0, r1);
        ((__nv_bfloat162*)(oh + (size_t)r * Dn))[t] = h2;
        ((__nv_bfloat162*)(ol + (size_t)r * Dn))[t] = l2;
        a0 += v.x; a1 += v.y;
    }
    g_pool[b][sl][2 * t]     = a0;
    g_pool[b][sl][2 * t + 1] = a1;
}

// ---------------- router finish: logits, softmax, argmax ------------------
__global__ __launch_bounds__(256) void router_finish(
    const float* __restrict__ Wp, const float* __restrict__ bp,
    float* __restrict__ probs_out, float* __restrict__ idx_out)
{
    int b = blockIdx.x;
    __shared__ float pooled[Dn];
    __shared__ float logits[En];
    for (int d = threadIdx.x; d < Dn; d += 256) {
        float s = 0.f;
        #pragma unroll
        for (int sl = 0; sl < 8; sl++) s += g_pool[b][sl][d];
        pooled[d] = s * (1.0f / (float)Tn);
    }
    __syncthreads();
    int w = threadIdx.x >> 5, lane = threadIdx.x & 31;
    if (w < En) {
        float s = 0.f;
        for (int d = lane; d < Dn; d += 32) s += pooled[d] * Wp[(size_t)d * En + w];
        #pragma unroll
        for (int o = 16; o > 0; o >>= 1) s += __shfl_xor_sync(0xffffffffu, s, o);
        if (lane == 0) logits[w] = s + bp[w];
    }
    __syncthreads();
    if (threadIdx.x == 0) {
        float m = logits[0]; int am = 0;
        #pragma unroll
        for (int e = 1; e < En; e++) if (logits[e] > m) { m = logits[e]; am = e; }
        float ex[En], den = 0.f;
        #pragma unroll
        for (int e = 0; e < En; e++) { ex[e] = expf(logits[e] - m); den += ex[e]; }
        float inv = 1.0f / den;
        #pragma unroll
        for (int e = 0; e < En; e++) probs_out[b * En + e] = ex[e] * inv;
        idx_out[b]  = (float)am;
        g_expert[b] = am;
    }
}

// ---------------- pre-pass: transpose + split W1 and W2 (one launch) ------
__global__ __launch_bounds__(256) void transpose_split_all(
    const float* __restrict__ W1, const float* __restrict__ W2)
{
    __shared__ float tile[32][33];
    bool isW1 = blockIdx.z < En;
    int e = isW1 ? blockIdx.z : blockIdx.z - En;
    int R = isW1 ? Dn : Hn;
    int C = isW1 ? Hn : Dn;
    int c0 = (isW1 ? blockIdx.x : blockIdx.y) * 32;
    int r0 = (isW1 ? blockIdx.y : blockIdx.x) * 32;
    const float* in = (isW1 ? W1 : W2) + (size_t)e * R * C;
    __nv_bfloat16* oh = (isW1 ? g_w1h : g_w2h);
    __nv_bfloat16* ol = (isW1 ? g_w1l : g_w2l);
    int tx = threadIdx.x & 31, ty = threadIdx.x >> 5;
    #pragma unroll
    for (int i = 0; i < 32; i += 8)
        tile[ty + i][tx] = in[(size_t)(r0 + ty + i) * C + (c0 + tx)];
    __syncthreads();
    size_t ob = (size_t)e * R * C;
    #pragma unroll
    for (int i = 0; i < 32; i += 8) {
        int oc = c0 + ty + i;
        float v = tile[tx][ty + i];
        __nv_bfloat16 h = __float2bfloat16(v);
        float resid = v - __bfloat162float(h);
        oh[ob + (size_t)oc * R + r0 + tx] = h;
        ol[ob + (size_t)oc * R + r0 + tx] = __float2bfloat16(resid);
    }
}

// ---------------- HMMA GEMM ------------------------------------------------
// C[b](M, Ntot) = act(A[b](M,K) @ Bt[e](Ntot,K)^T + bias[e]), 3-term hi/lo.
// 3-stage cp.async pipeline, ONE __syncthreads per chunk, fragment reuse
// across term passes: (Ah·Bh), (Ah·Bl) share a-frags; (Al·Bh) reuses b_h.
#define KC 32
#define ASTRIDE 80                    // bytes per smem row (32 bf16 + 16B pad)

template <int MT_, int NT_, int THREADS>
__device__ __forceinline__ void load_chunk2(
    uint32_t stageBase,
    const __nv_bfloat16* __restrict__ Ah, const __nv_bfloat16* __restrict__ Al,
    const __nv_bfloat16* __restrict__ Bh, const __nv_bfloat16* __restrict__ Bl,
    int K, int k0, int tid)
{
    constexpr int ASEGS = MT_ * 4;          // 16B segments per A tile
    #pragma unroll
    for (int idx = tid; idx < 2 * ASEGS; idx += THREADS) {
        int tl = idx / ASEGS;
        int rem = idx - tl * ASEGS;
        int r = rem >> 2, seg = rem & 3;
        const __nv_bfloat16* src = (tl ? Al : Ah) + (size_t)r * K + k0 + seg * 8;
        cp16(stageBase + tl * MT_ * ASTRIDE + r * ASTRIDE + seg * 16, src);
    }
    constexpr int BSEGS = NT_ * 4;
    uint32_t bbase = stageBase + 2 * MT_ * ASTRIDE;
    #pragma unroll
    for (int idx = tid; idx < 2 * BSEGS; idx += THREADS) {
        int tl = idx / BSEGS;
        int rem = idx - tl * BSEGS;
        int r = rem >> 2, seg = rem & 3;
        const __nv_bfloat16* src = (tl ? Bl : Bh) + (size_t)r * K + k0 + seg * 8;
        cp16(bbase + tl * NT_ * ASTRIDE + r * ASTRIDE + seg * 16, src);
    }
}

template <int MT_, int NT_, int WGM, int THREADS, int MINCTA, bool FUSE1>
__global__ __launch_bounds__(THREADS, MINCTA) void mma_gemm(
    const __nv_bfloat16* __restrict__ Ah, const __nv_bfloat16* __restrict__ Al,
    const __nv_bfloat16* __restrict__ Bh, const __nv_bfloat16* __restrict__ Bl,
    const float* __restrict__ bias,
    __nv_bfloat16* __restrict__ out_h, __nv_bfloat16* __restrict__ out_l,
    float* __restrict__ out_f, int K, int Ntot)
{
    constexpr int NWARPS = THREADS / 32;
    constexpr int WGN    = NWARPS / WGM;
    constexpr int WCOLS  = NT_ / WGN;       // cols per warp
    constexpr int NJP    = WCOLS / 16;      // b ldmatrix.x4 per ks
    constexpr int STAGE_ = (2 * MT_ + 2 * NT_) * ASTRIDE;

    extern __shared__ char smem[];
    uint32_t sb = smem_u32(smem);
    int tid = threadIdx.x, wid = tid >> 5, lane = tid & 31;
    int warp_m = wid % WGM, warp_n = wid / WGM;
    int b = blockIdx.z, e = g_expert[b];
    int m0 = blockIdx.y * MT_, n0 = blockIdx.x * NT_;

    const __nv_bfloat16* Abh = Ah + (size_t)b * Tn * K + (size_t)m0 * K;
    const __nv_bfloat16* Abl = Al + (size_t)b * Tn * K + (size_t)m0 * K;
    const __nv_bfloat16* Bbh = Bh + (size_t)e * Ntot * K + (size_t)n0 * K;
    const __nv_bfloat16* Bbl = Bl + (size_t)e * Ntot * K + (size_t)n0 * K;

    const int nc = K / KC;

    float acc[4][2 * NJP][4];
    #pragma unroll
    for (int i = 0; i < 4; i++)
        #pragma unroll
        for (int j = 0; j < 2 * NJP; j++)
            #pragma unroll
            for (int q = 0; q < 4; q++) acc[i][j][q] = 0.f;

    load_chunk2<MT_, NT_, THREADS>(sb,          Abh, Abl, Bbh, Bbl, K, 0,  tid); CP_COMMIT();
    load_chunk2<MT_, NT_, THREADS>(sb + STAGE_, Abh, Abl, Bbh, Bbl, K, KC, tid); CP_COMMIT();

    uint32_t lm_row = (lane & 15), lm_half = (lane >> 4) << 4;
    uint32_t aoffH = lm_row * ASTRIDE + lm_half + (warp_m * 64) * ASTRIDE;
    uint32_t aoffL = aoffH + MT_ * ASTRIDE;
    uint32_t boffH = 2 * MT_ * ASTRIDE + lm_row * ASTRIDE + lm_half + (warp_n * WCOLS) * ASTRIDE;
    uint32_t boffL = boffH + NT_ * ASTRIDE;

    for (int i = 0; i < nc; i++) {
        if (i < nc - 1) CP_WAIT1(); else CP_WAIT0();   // chunk i landed (mine)
        __syncthreads();                               // everyone's chunk i visible;
                                                       // everyone past compute(i-1)
        if (i + 2 < nc) {
            load_chunk2<MT_, NT_, THREADS>(sb + ((i + 2) % 3) * STAGE_,
                                           Abh, Abl, Bbh, Bbl, K, (i + 2) * KC, tid);
            CP_COMMIT();
        }

        uint32_t stg = sb + (i % 3) * STAGE_;
        #pragma unroll
        for (int ks = 0; ks < 2; ks++) {
            uint32_t a[4][4], bh[NJP][4], bl[NJP][4];
            #pragma unroll
            for (int ia = 0; ia < 4; ia++)
                ldmx4(a[ia], stg + aoffH + ia * 16 * ASTRIDE + ks * 32);
            #pragma unroll
            for (int jp = 0; jp < NJP; jp++)
                ldmx4(bh[jp], stg + boffH + jp * 16 * ASTRIDE + ks * 32);
            #pragma unroll
            for (int jp = 0; jp < NJP; jp++)
                ldmx4(bl[jp], stg + boffL + jp * 16 * ASTRIDE + ks * 32);
            // pass 0: Ah x Bh
            #pragma unroll
            for (int ia = 0; ia < 4; ia++)
                #pragma unroll
                for (int j = 0; j < 2 * NJP; j++) {
                    int jp = j >> 1, hi = j & 1;
                    mma16816(acc[ia][j], a[ia], bh[jp][hi], bh[jp][hi + 2]);
                }
            // pass 1: Ah x Bl (reuse a)
            #pragma unroll
            for (int ia = 0; ia < 4; ia++)
                #pragma unroll
                for (int j = 0; j < 2 * NJP; j++) {
                    int jp = j >> 1, hi = j & 1;
                    mma16816(acc[ia][j], a[ia], bl[jp][hi], bl[jp][hi + 2]);
                }
            // reload a <- Al, pass 2: Al x Bh (reuse bh)
            #pragma unroll
            for (int ia = 0; ia < 4; ia++)
                ldmx4(a[ia], stg + aoffL + ia * 16 * ASTRIDE + ks * 32);
            #pragma unroll
            for (int ia = 0; ia < 4; ia++)
                #pragma unroll
                for (int j = 0; j < 2 * NJP; j++) {
                    int jp = j >> 1, hi = j & 1;
                    mma16816(acc[ia][j], a[ia], bh[jp][hi], bh[jp][hi + 2]);
                }
        }
    }

    // ------------- epilogue -------------
    int mrow = m0 + warp_m * 64 + (lane >> 2);
    int ncol = n0 + warp_n * WCOLS + (lane & 3) * 2;
    const float* bb = bias + (size_t)e * Ntot;

    #pragma unroll
    for (int ia = 0; ia < 4; ia++) {
        #pragma unroll
        for (int j = 0; j < 2 * NJP; j++) {
            int n = ncol + j * 8;
            float2 b2 = *(const float2*)(bb + n);
            #pragma unroll
            for (int half = 0; half < 2; half++) {
                int m = mrow + ia * 16 + half * 8;
                float v0 = acc[ia][j][2 * half]     + b2.x;
                float v1 = acc[ia][j][2 * half + 1] + b2.y;
                if (FUSE1) {
                    v0 = fmaxf(v0, 0.f); v1 = fmaxf(v1, 0.f);
                    __nv_bfloat162 h2 = __floats2bfloat162_rn(v0, v1);
                    float r0 = v0 - __bfloat162float(h2.x);
                    float r1 = v1 - __bfloat162float(h2.y);
                    __nv_bfloat162 l2 = __floats2bfloat162_rn(r0, r1);
                    *(__nv_bfloat162*)(out_h + ((size_t)b * Tn + m) * Ntot + n) = h2;
                    *(__nv_bfloat162*)(out_l + ((size_t)b * Tn + m) * Ntot + n) = l2;
                } else {
                    float2 o = make_float2(v0, v1);
                    *(float2*)(out_f + ((size_t)b * Tn + m) * Ntot + n) = o;
                }
            }
        }
    }
}

// ---------------------------------------------------------------------------
extern "C" void kernel_launch(void* const* d_in, const int* in_sizes, int n_in,
                              void* d_out, int out_size)
{
    const float* x  = (const float*)d_in[0];
    const float* Wp = (const float*)d_in[1];
    const float* bp = (const float*)d_in[2];
    const float* W1 = (const float*)d_in[3];
    const float* b1 = (const float*)d_in[4];
    const float* W2 = (const float*)d_in[5];
    const float* b2 = (const float*)d_in[6];

    float* out   = (float*)d_out;
    float* probs = out + (size_t)Bsz * Tn * Dn;
    float* idx   = probs + (size_t)Bsz * En;

    __nv_bfloat16 *xh, *xl, *w1h, *w1l, *w2h, *w2l, *hh, *hl;
    cudaGetSymbolAddress((void**)&xh,  g_xh);
    cudaGetSymbolAddress((void**)&xl,  g_xl);
    cudaGetSymbolAddress((void**)&w1h, g_w1h);
    cudaGetSymbolAddress((void**)&w1l, g_w1l);
    cudaGetSymbolAddress((void**)&w2h, g_w2h);
    cudaGetSymbolAddress((void**)&w2l, g_w2l);
    cudaGetSymbolAddress((void**)&hh,  g_hh);
    cudaGetSymbolAddress((void**)&hl,  g_hl);

    // GEMM1: 128x256, 512 thr (16 warps 2x8, warp 64x32), 1 CTA/SM.
    // GEMM2: 64x128, 256 thr (8 warps 1x8, warp 64x16), 2 CTA/SM.
    constexpr int SMEM1 = 3 * (2 * 128 + 2 * 256) * ASTRIDE;   // 184320
    constexpr int SMEM2 = 3 * (2 * 64 + 2 * 128) * ASTRIDE;    // 92160
    cudaFuncSetAttribute((const void*)mma_gemm<128, 256, 2, 512, 1, true>,
                         cudaFuncAttributeMaxDynamicSharedMemorySize, SMEM1);
    cudaFuncSetAttribute((const void*)mma_gemm<64, 128, 1, 256, 2, false>,
                         cudaFuncAttributeMaxDynamicSharedMemorySize, SMEM2);

    split_x_pool<<<dim3(Bsz, 8), 256>>>(x);
    router_finish<<<Bsz, 256>>>(Wp, bp, probs, idx);
    transpose_split_all<<<dim3(Hn / 32, Dn / 32, 2 * En), 256>>>(W1, W2);

    // GEMM1: h = relu(x @ W1[e] + b1[e]),  K=D, Ntot=H  -> 1024 CTAs
    mma_gemm<128, 256, 2, 512, 1, true><<<dim3(Hn / 256, Tn / 128, Bsz), 512, SMEM1>>>(
        xh, xl, w1h, w1l, b1, hh, hl, nullptr, Dn, Hn);
    // GEMM2: out = h @ W2[e] + b2[e],      K=H, Ntot=D  -> 1024 CTAs, 2/SM
    mma_gemm<64, 128, 1, 256, 2, false><<<dim3(Dn / 128, Tn / 64, Bsz), 256, SMEM2>>>(
        hh, hl, w2h, w2l, b2, nullptr, nullptr, out, Hn, Dn);
}

// round 11
// speedup vs baseline: 4.3425x; 1.3928x over previous
#include <cuda_runtime.h>
#include <cuda_fp16.h>
#include <cstdint>
#include <math.h>

#define Bsz 32
#define Tn  512
#define Dn  512
#define En  8
#define Hn  2048

// ---------------- device scratch (static: allocation-guard safe) ----------
__device__ __align__(16) __half g_xh[(size_t)Bsz*Tn*Dn];
__device__ __align__(16) __half g_xl[(size_t)Bsz*Tn*Dn];
__device__ __align__(16) __half g_w1t[(size_t)En*Hn*Dn];   // [E][H][D] (N-major) fp16
__device__ __align__(16) __half g_w2t[(size_t)En*Dn*Hn];   // [E][D][H] (N-major) fp16
__device__ __align__(16) __half g_hh[(size_t)Bsz*Tn*Hn];
__device__ __align__(16) __half g_hl[(size_t)Bsz*Tn*Hn];
__device__ float g_pool[Bsz][8][Dn];
__device__ int   g_expert[Bsz];

// ---------------- small PTX helpers ---------------------------------------
__device__ __forceinline__ uint32_t smem_u32(const void* p) {
    uint32_t a;
    asm("{ .reg .u64 t; cvta.to.shared.u64 t, %1; cvt.u32.u64 %0, t; }" : "=r"(a) : "l"(p));
    return a;
}
__device__ __forceinline__ void cp16(uint32_t dst, const void* src) {
    asm volatile("cp.async.cg.shared.global [%0], [%1], 16;" :: "r"(dst), "l"(__cvta_generic_to_global(src)));
}
#define CP_COMMIT()  asm volatile("cp.async.commit_group;" ::: "memory")
#define CP_WAIT0()   asm volatile("cp.async.wait_group 0;" ::: "memory")
#define CP_WAIT1()   asm volatile("cp.async.wait_group 1;" ::: "memory")
#define CP_WAIT2()   asm volatile("cp.async.wait_group 2;" ::: "memory")

__device__ __forceinline__ void ldmx4(uint32_t* r, uint32_t addr) {
    asm volatile("ldmatrix.sync.aligned.m8n8.x4.shared.b16 {%0,%1,%2,%3}, [%4];"
                 : "=r"(r[0]), "=r"(r[1]), "=r"(r[2]), "=r"(r[3]) : "r"(addr));
}
__device__ __forceinline__ void mma16816f(float* c, const uint32_t* a, uint32_t b0, uint32_t b1) {
    asm volatile("mma.sync.aligned.m16n8k16.row.col.f32.f16.f16.f32 "
                 "{%0,%1,%2,%3}, {%4,%5,%6,%7}, {%8,%9}, {%0,%1,%2,%3};"
                 : "+f"(c[0]), "+f"(c[1]), "+f"(c[2]), "+f"(c[3])
                 : "r"(a[0]), "r"(a[1]), "r"(a[2]), "r"(a[3]), "r"(b0), "r"(b1));
}

// ---------------- pre-pass: split x to fp16 hi/lo + pooled partials -------
__global__ __launch_bounds__(256) void split_x_pool(const float* __restrict__ x) {
    int b = blockIdx.x, sl = blockIdx.y;
    const float* xb = x + (size_t)b * Tn * Dn + (size_t)sl * 64 * Dn;
    __half* oh = g_xh + (size_t)b * Tn * Dn + (size_t)sl * 64 * Dn;
    __half* ol = g_xl + (size_t)b * Tn * Dn + (size_t)sl * 64 * Dn;
    int t = threadIdx.x;
    float a0 = 0.f, a1 = 0.f;
    for (int r = 0; r < 64; r++) {
        float2 v = ((const float2*)(xb + (size_t)r * Dn))[t];
        __half2 h2 = __floats2half2_rn(v.x, v.y);
        float r0 = v.x - __low2float(h2);
        float r1 = v.y - __high2float(h2);
        __half2 l2 = __floats2half2_rn(r0, r1);
        ((__half2*)(oh + (size_t)r * Dn))[t] = h2;
        ((__half2*)(ol + (size_t)r * Dn))[t] = l2;
        a0 += v.x; a1 += v.y;
    }
    g_pool[b][sl][2 * t]     = a0;
    g_pool[b][sl][2 * t + 1] = a1;
}

// ---------------- router finish: logits, softmax, argmax ------------------
__global__ __launch_bounds__(256) void router_finish(
    const float* __restrict__ Wp, const float* __restrict__ bp,
    float* __restrict__ probs_out, float* __restrict__ idx_out)
{
    int b = blockIdx.x;
    __shared__ float pooled[Dn];
    __shared__ float logits[En];
    for (int d = threadIdx.x; d < Dn; d += 256) {
        float s = 0.f;
        #pragma unroll
        for (int sl = 0; sl < 8; sl++) s += g_pool[b][sl][d];
        pooled[d] = s * (1.0f / (float)Tn);
    }
    __syncthreads();
    int w = threadIdx.x >> 5, lane = threadIdx.x & 31;
    if (w < En) {
        float s = 0.f;
        for (int d = lane; d < Dn; d += 32) s += pooled[d] * Wp[(size_t)d * En + w];
        #pragma unroll
        for (int o = 16; o > 0; o >>= 1) s += __shfl_xor_sync(0xffffffffu, s, o);
        if (lane == 0) logits[w] = s + bp[w];
    }
    __syncthreads();
    if (threadIdx.x == 0) {
        float m = logits[0]; int am = 0;
        #pragma unroll
        for (int e = 1; e < En; e++) if (logits[e] > m) { m = logits[e]; am = e; }
        float ex[En], den = 0.f;
        #pragma unroll
        for (int e = 0; e < En; e++) { ex[e] = expf(logits[e] - m); den += ex[e]; }
        float inv = 1.0f / den;
        #pragma unroll
        for (int e = 0; e < En; e++) probs_out[b * En + e] = ex[e] * inv;
        idx_out[b]  = (float)am;
        g_expert[b] = am;
    }
}

// ---------------- pre-pass: transpose W1 and W2 to fp16 (one launch) ------
__global__ __launch_bounds__(256) void transpose_all(
    const float* __restrict__ W1, const float* __restrict__ W2)
{
    __shared__ float tile[32][33];
    bool isW1 = blockIdx.z < En;
    int e = isW1 ? blockIdx.z : blockIdx.z - En;
    int R = isW1 ? Dn : Hn;
    int C = isW1 ? Hn : Dn;
    int c0 = (isW1 ? blockIdx.x : blockIdx.y) * 32;
    int r0 = (isW1 ? blockIdx.y : blockIdx.x) * 32;
    const float* in = (isW1 ? W1 : W2) + (size_t)e * R * C;
    __half* oh = (isW1 ? g_w1t : g_w2t);
    int tx = threadIdx.x & 31, ty = threadIdx.x >> 5;
    #pragma unroll
    for (int i = 0; i < 32; i += 8)
        tile[ty + i][tx] = in[(size_t)(r0 + ty + i) * C + (c0 + tx)];
    __syncthreads();
    size_t ob = (size_t)e * R * C;
    #pragma unroll
    for (int i = 0; i < 32; i += 8) {
        int oc = c0 + ty + i;
        oh[ob + (size_t)oc * R + r0 + tx] = __float2half_rn(tile[tx][ty + i]);
    }
}

// ---------------- HMMA GEMM (2-term fp16) ----------------------------------
// C[b](M, Ntot) = act(A[b](M,K) @ Bt[e](Ntot,K)^T + bias[e])
// A = Ah + Al (fp16 hi/lo), B single fp16. 2 MMA passes: Ah·B, Al·B.
// 4-stage cp.async pipeline, one __syncthreads per chunk.
#define KC 32
#define ASTRIDE 80                    // bytes per smem row (32 fp16 + 16B pad)
#define NSTAGE 4

template <int MT_, int NT_, int THREADS>
__device__ __forceinline__ void load_chunk2(
    uint32_t stageBase,
    const __half* __restrict__ Ah, const __half* __restrict__ Al,
    const __half* __restrict__ Bt, int K, int k0, int tid)
{
    constexpr int ASEGS = MT_ * 4;          // 16B segments per A tile
    #pragma unroll
    for (int idx = tid; idx < 2 * ASEGS; idx += THREADS) {
        int tl = idx / ASEGS;
        int rem = idx - tl * ASEGS;
        int r = rem >> 2, seg = rem & 3;
        const __half* src = (tl ? Al : Ah) + (size_t)r * K + k0 + seg * 8;
        cp16(stageBase + tl * MT_ * ASTRIDE + r * ASTRIDE + seg * 16, src);
    }
    constexpr int BSEGS = NT_ * 4;
    uint32_t bbase = stageBase + 2 * MT_ * ASTRIDE;
    #pragma unroll
    for (int idx = tid; idx < BSEGS; idx += THREADS) {
        int r = idx >> 2, seg = idx & 3;
        cp16(bbase + r * ASTRIDE + seg * 16, Bt + (size_t)r * K + k0 + seg * 8);
    }
}

template <int MT_, int NT_, int WGM, int THREADS, int MINCTA, bool FUSE1>
__global__ __launch_bounds__(THREADS, MINCTA) void mma_gemm(
    const __half* __restrict__ Ah, const __half* __restrict__ Al,
    const __half* __restrict__ Bt, const float* __restrict__ bias,
    __half* __restrict__ out_h, __half* __restrict__ out_l,
    float* __restrict__ out_f, int K, int Ntot)
{
    constexpr int NWARPS = THREADS / 32;
    constexpr int WGN    = NWARPS / WGM;
    constexpr int WCOLS  = NT_ / WGN;       // cols per warp
    constexpr int NJP    = WCOLS / 16;      // b ldmatrix.x4 per ks
    constexpr int STAGE_ = (2 * MT_ + NT_) * ASTRIDE;

    extern __shared__ char smem[];
    uint32_t sb = smem_u32(smem);
    int tid = threadIdx.x, wid = tid >> 5, lane = tid & 31;
    int warp_m = wid % WGM, warp_n = wid / WGM;
    int b = blockIdx.z, e = g_expert[b];
    int m0 = blockIdx.y * MT_, n0 = blockIdx.x * NT_;

    const __half* Abh = Ah + (size_t)b * Tn * K + (size_t)m0 * K;
    const __half* Abl = Al + (size_t)b * Tn * K + (size_t)m0 * K;
    const __half* Bb  = Bt + (size_t)e * Ntot * K + (size_t)n0 * K;

    const int nc = K / KC;

    float acc[4][2 * NJP][4];
    #pragma unroll
    for (int i = 0; i < 4; i++)
        #pragma unroll
        for (int j = 0; j < 2 * NJP; j++)
            #pragma unroll
            for (int q = 0; q < 4; q++) acc[i][j][q] = 0.f;

    // prologue: 3 chunks in flight
    load_chunk2<MT_, NT_, THREADS>(sb,              Abh, Abl, Bb, K, 0,      tid); CP_COMMIT();
    load_chunk2<MT_, NT_, THREADS>(sb + STAGE_,     Abh, Abl, Bb, K, KC,     tid); CP_COMMIT();
    load_chunk2<MT_, NT_, THREADS>(sb + 2 * STAGE_, Abh, Abl, Bb, K, 2 * KC, tid); CP_COMMIT();

    uint32_t lm_row = (lane & 15), lm_half = (lane >> 4) << 4;
    uint32_t aoffH = lm_row * ASTRIDE + lm_half + (warp_m * 64) * ASTRIDE;
    uint32_t aoffL = aoffH + MT_ * ASTRIDE;
    uint32_t boff  = 2 * MT_ * ASTRIDE + lm_row * ASTRIDE + lm_half + (warp_n * WCOLS) * ASTRIDE;

    for (int i = 0; i < nc; i++) {
        if (i < nc - 2)      CP_WAIT2();           // chunk i landed
        else if (i == nc - 2) CP_WAIT1();
        else                  CP_WAIT0();
        __syncthreads();                           // chunk i visible to all;
                                                   // all warps past compute(i-1)
        if (i + 3 < nc) {
            load_chunk2<MT_, NT_, THREADS>(sb + ((i + 3) % NSTAGE) * STAGE_,
                                           Abh, Abl, Bb, K, (i + 3) * KC, tid);
            CP_COMMIT();
        }

        uint32_t stg = sb + (i % NSTAGE) * STAGE_;
        #pragma unroll
        for (int ks = 0; ks < 2; ks++) {
            uint32_t a[4][4], bq[NJP][4];
            #pragma unroll
            for (int jp = 0; jp < NJP; jp++)
                ldmx4(bq[jp], stg + boff + jp * 16 * ASTRIDE + ks * 32);
            #pragma unroll
            for (int ia = 0; ia < 4; ia++)
                ldmx4(a[ia], stg + aoffH + ia * 16 * ASTRIDE + ks * 32);
            // pass 0: Ah x B
            #pragma unroll
            for (int ia = 0; ia < 4; ia++)
                #pragma unroll
                for (int j = 0; j < 2 * NJP; j++) {
                    int jp = j >> 1, hi = j & 1;
                    mma16816f(acc[ia][j], a[ia], bq[jp][hi], bq[jp][hi + 2]);
                }
            // reload a <- Al, pass 1: Al x B (reuse b frags)
            #pragma unroll
            for (int ia = 0; ia < 4; ia++)
                ldmx4(a[ia], stg + aoffL + ia * 16 * ASTRIDE + ks * 32);
            #pragma unroll
            for (int ia = 0; ia < 4; ia++)
                #pragma unroll
                for (int j = 0; j < 2 * NJP; j++) {
                    int jp = j >> 1, hi = j & 1;
                    mma16816f(acc[ia][j], a[ia], bq[jp][hi], bq[jp][hi + 2]);
                }
        }
    }

    // ------------- epilogue -------------
    int mrow = m0 + warp_m * 64 + (lane >> 2);
    int ncol = n0 + warp_n * WCOLS + (lane & 3) * 2;
    const float* bb = bias + (size_t)e * Ntot;

    #pragma unroll
    for (int ia = 0; ia < 4; ia++) {
        #pragma unroll
        for (int j = 0; j < 2 * NJP; j++) {
            int n = ncol + j * 8;
            float2 b2 = *(const float2*)(bb + n);
            #pragma unroll
            for (int half = 0; half < 2; half++) {
                int m = mrow + ia * 16 + half * 8;
                float v0 = acc[ia][j][2 * half]     + b2.x;
                float v1 = acc[ia][j][2 * half + 1] + b2.y;
                if (FUSE1) {
                    v0 = fmaxf(v0, 0.f); v1 = fmaxf(v1, 0.f);
                    __half2 h2 = __floats2half2_rn(v0, v1);
                    float r0 = v0 - __low2float(h2);
                    float r1 = v1 - __high2float(h2);
                    __half2 l2 = __floats2half2_rn(r0, r1);
                    *(__half2*)(out_h + ((size_t)b * Tn + m) * Ntot + n) = h2;
                    *(__half2*)(out_l + ((size_t)b * Tn + m) * Ntot + n) = l2;
                } else {
                    float2 o = make_float2(v0, v1);
                    *(float2*)(out_f + ((size_t)b * Tn + m) * Ntot + n) = o;
                }
            }
        }
    }
}

// ---------------------------------------------------------------------------
extern "C" void kernel_launch(void* const* d_in, const int* in_sizes, int n_in,
                              void* d_out, int out_size)
{
    const float* x  = (const float*)d_in[0];
    const float* Wp = (const float*)d_in[1];
    const float* bp = (const float*)d_in[2];
    const float* W1 = (const float*)d_in[3];
    const float* b1 = (const float*)d_in[4];
    const float* W2 = (const float*)d_in[5];
    const float* b2 = (const float*)d_in[6];

    float* out   = (float*)d_out;
    float* probs = out + (size_t)Bsz * Tn * Dn;
    float* idx   = probs + (size_t)Bsz * En;

    __half *xh, *xl, *w1t, *w2t, *hh, *hl;
    cudaGetSymbolAddress((void**)&xh,  g_xh);
    cudaGetSymbolAddress((void**)&xl,  g_xl);
    cudaGetSymbolAddress((void**)&w1t, g_w1t);
    cudaGetSymbolAddress((void**)&w2t, g_w2t);
    cudaGetSymbolAddress((void**)&hh,  g_hh);
    cudaGetSymbolAddress((void**)&hl,  g_hl);

    // GEMM1: 128x256, 512 thr (16 warps 2x8, warp 64x32), 1 CTA/SM, 4 stages.
    // GEMM2: 64x128, 256 thr (8 warps 1x8, warp 64x16), 2 CTA/SM, 4 stages.
    constexpr int SMEM1 = NSTAGE * (2 * 128 + 256) * ASTRIDE;   // 163840
    constexpr int SMEM2 = NSTAGE * (2 * 64 + 128) * ASTRIDE;    // 81920
    cudaFuncSetAttribute((const void*)mma_gemm<128, 256, 2, 512, 1, true>,
                         cudaFuncAttributeMaxDynamicSharedMemorySize, SMEM1);
    cudaFuncSetAttribute((const void*)mma_gemm<64, 128, 1, 256, 2, false>,
                         cudaFuncAttributeMaxDynamicSharedMemorySize, SMEM2);

    split_x_pool<<<dim3(Bsz, 8), 256>>>(x);
    router_finish<<<Bsz, 256>>>(Wp, bp, probs, idx);
    transpose_all<<<dim3(Hn / 32, Dn / 32, 2 * En), 256>>>(W1, W2);

    // GEMM1: h = relu(x @ W1[e] + b1[e]),  K=D, Ntot=H  -> 1024 CTAs
    mma_gemm<128, 256, 2, 512, 1, true><<<dim3(Hn / 256, Tn / 128, Bsz), 512, SMEM1>>>(
        xh, xl, w1t, b1, hh, hl, nullptr, Dn, Hn);
    // GEMM2: out = h @ W2[e] + b2[e],      K=H, Ntot=D  -> 1024 CTAs, 2/SM
    mma_gemm<64, 128, 1, 256, 2, false><<<dim3(Dn / 128, Tn / 64, Bsz), 256, SMEM2>>>(
        hh, hl, w2t, b2, nullptr, nullptr, out, Hn, Dn);
}

// round 12
// speedup vs baseline: 7.3719x; 1.6976x over previous
#include <cuda_runtime.h>
#include <cuda_fp16.h>
#include <cstdint>
#include <math.h>

#define Bsz 32
#define Tn  512
#define Dn  512
#define En  8
#define Hn  2048

// ---------------- device scratch (static: allocation-guard safe) ----------
__device__ __align__(16) __half g_x16[(size_t)Bsz*Tn*Dn];
__device__ __align__(16) __half g_w1t[(size_t)En*Hn*Dn];   // [E][H][D] (N-major) fp16
__device__ __align__(16) __half g_w2t[(size_t)En*Dn*Hn];   // [E][D][H] (N-major) fp16
__device__ __align__(16) __half g_h16[(size_t)Bsz*Tn*Hn];
__device__ float g_pool[Bsz][8][Dn];
__device__ int   g_expert[Bsz];

// ---------------- small PTX helpers ---------------------------------------
__device__ __forceinline__ uint32_t smem_u32(const void* p) {
    uint32_t a;
    asm("{ .reg .u64 t; cvta.to.shared.u64 t, %1; cvt.u32.u64 %0, t; }" : "=r"(a) : "l"(p));
    return a;
}
__device__ __forceinline__ void cp16(uint32_t dst, const void* src) {
    asm volatile("cp.async.cg.shared.global [%0], [%1], 16;" :: "r"(dst), "l"(__cvta_generic_to_global(src)));
}
#define CP_COMMIT()  asm volatile("cp.async.commit_group;" ::: "memory")
#define CP_WAIT0()   asm volatile("cp.async.wait_group 0;" ::: "memory")
#define CP_WAIT1()   asm volatile("cp.async.wait_group 1;" ::: "memory")
#define CP_WAIT2()   asm volatile("cp.async.wait_group 2;" ::: "memory")

__device__ __forceinline__ void ldmx4(uint32_t* r, uint32_t addr) {
    asm volatile("ldmatrix.sync.aligned.m8n8.x4.shared.b16 {%0,%1,%2,%3}, [%4];"
                 : "=r"(r[0]), "=r"(r[1]), "=r"(r[2]), "=r"(r[3]) : "r"(addr));
}
__device__ __forceinline__ void mma16816f(float* c, const uint32_t* a, uint32_t b0, uint32_t b1) {
    asm volatile("mma.sync.aligned.m16n8k16.row.col.f32.f16.f16.f32 "
                 "{%0,%1,%2,%3}, {%4,%5,%6,%7}, {%8,%9}, {%0,%1,%2,%3};"
                 : "+f"(c[0]), "+f"(c[1]), "+f"(c[2]), "+f"(c[3])
                 : "r"(a[0]), "r"(a[1]), "r"(a[2]), "r"(a[3]), "r"(b0), "r"(b1));
}

// ---------------- pre-pass: x -> fp16 + pooled partials -------------------
__global__ __launch_bounds__(256) void convert_x_pool(const float* __restrict__ x) {
    int b = blockIdx.x, sl = blockIdx.y;
    const float* xb = x + (size_t)b * Tn * Dn + (size_t)sl * 64 * Dn;
    __half* oh = g_x16 + (size_t)b * Tn * Dn + (size_t)sl * 64 * Dn;
    int t = threadIdx.x;
    float a0 = 0.f, a1 = 0.f;
    for (int r = 0; r < 64; r++) {
        float2 v = ((const float2*)(xb + (size_t)r * Dn))[t];
        ((__half2*)(oh + (size_t)r * Dn))[t] = __floats2half2_rn(v.x, v.y);
        a0 += v.x; a1 += v.y;
    }
    g_pool[b][sl][2 * t]     = a0;
    g_pool[b][sl][2 * t + 1] = a1;
}

// ---------------- router finish: logits, softmax, argmax ------------------
__global__ __launch_bounds__(256) void router_finish(
    const float* __restrict__ Wp, const float* __restrict__ bp,
    float* __restrict__ probs_out, float* __restrict__ idx_out)
{
    int b = blockIdx.x;
    __shared__ float pooled[Dn];
    __shared__ float logits[En];
    for (int d = threadIdx.x; d < Dn; d += 256) {
        float s = 0.f;
        #pragma unroll
        for (int sl = 0; sl < 8; sl++) s += g_pool[b][sl][d];
        pooled[d] = s * (1.0f / (float)Tn);
    }
    __syncthreads();
    int w = threadIdx.x >> 5, lane = threadIdx.x & 31;
    if (w < En) {
        float s = 0.f;
        for (int d = lane; d < Dn; d += 32) s += pooled[d] * Wp[(size_t)d * En + w];
        #pragma unroll
        for (int o = 16; o > 0; o >>= 1) s += __shfl_xor_sync(0xffffffffu, s, o);
        if (lane == 0) logits[w] = s + bp[w];
    }
    __syncthreads();
    if (threadIdx.x == 0) {
        float m = logits[0]; int am = 0;
        #pragma unroll
        for (int e = 1; e < En; e++) if (logits[e] > m) { m = logits[e]; am = e; }
        float ex[En], den = 0.f;
        #pragma unroll
        for (int e = 0; e < En; e++) { ex[e] = expf(logits[e] - m); den += ex[e]; }
        float inv = 1.0f / den;
        #pragma unroll
        for (int e = 0; e < En; e++) probs_out[b * En + e] = ex[e] * inv;
        idx_out[b]  = (float)am;
        g_expert[b] = am;
    }
}

// ---------------- pre-pass: transpose W1 and W2 to fp16 (one launch) ------
__global__ __launch_bounds__(256) void transpose_all(
    const float* __restrict__ W1, const float* __restrict__ W2)
{
    __shared__ float tile[32][33];
    bool isW1 = blockIdx.z < En;
    int e = isW1 ? blockIdx.z : blockIdx.z - En;
    int R = isW1 ? Dn : Hn;
    int C = isW1 ? Hn : Dn;
    int c0 = (isW1 ? blockIdx.x : blockIdx.y) * 32;
    int r0 = (isW1 ? blockIdx.y : blockIdx.x) * 32;
    const float* in = (isW1 ? W1 : W2) + (size_t)e * R * C;
    __half* oh = (isW1 ? g_w1t : g_w2t);
    int tx = threadIdx.x & 31, ty = threadIdx.x >> 5;
    #pragma unroll
    for (int i = 0; i < 32; i += 8)
        tile[ty + i][tx] = in[(size_t)(r0 + ty + i) * C + (c0 + tx)];
    __syncthreads();
    size_t ob = (size_t)e * R * C;
    #pragma unroll
    for (int i = 0; i < 32; i += 8) {
        int oc = c0 + ty + i;
        oh[ob + (size_t)oc * R + r0 + tx] = __float2half_rn(tile[tx][ty + i]);
    }
}

// ---------------- HMMA GEMM (single-term fp16) ------------------------------
// C[b](M, Ntot) = act(A[b](M,K) @ Bt[e](Ntot,K)^T + bias[e])
// A, B single fp16; fp32 accumulate. 4-stage cp.async, 1 sync per chunk.
#define KC 32
#define ASTRIDE 80                    // bytes per smem row (32 fp16 + 16B pad)
#define NSTAGE 4

template <int MT_, int NT_, int THREADS>
__device__ __forceinline__ void load_chunk2(
    uint32_t stageBase, const __half* __restrict__ A,
    const __half* __restrict__ Bt, int K, int k0, int tid)
{
    constexpr int ASEGS = MT_ * 4;          // 16B segments per A tile
    #pragma unroll
    for (int idx = tid; idx < ASEGS; idx += THREADS) {
        int r = idx >> 2, seg = idx & 3;
        cp16(stageBase + r * ASTRIDE + seg * 16, A + (size_t)r * K + k0 + seg * 8);
    }
    constexpr int BSEGS = NT_ * 4;
    uint32_t bbase = stageBase + MT_ * ASTRIDE;
    #pragma unroll
    for (int idx = tid; idx < BSEGS; idx += THREADS) {
        int r = idx >> 2, seg = idx & 3;
        cp16(bbase + r * ASTRIDE + seg * 16, Bt + (size_t)r * K + k0 + seg * 8);
    }
}

template <int MT_, int NT_, int WGM, int THREADS, int MINCTA, bool FUSE1>
__global__ __launch_bounds__(THREADS, MINCTA) void mma_gemm(
    const __half* __restrict__ A, const __half* __restrict__ Bt,
    const float* __restrict__ bias,
    __half* __restrict__ out_h, float* __restrict__ out_f, int K, int Ntot)
{
    constexpr int NWARPS = THREADS / 32;
    constexpr int WGN    = NWARPS / WGM;
    constexpr int WCOLS  = NT_ / WGN;       // cols per warp
    constexpr int NJP    = WCOLS / 16;      // b ldmatrix.x4 per ks
    constexpr int STAGE_ = (MT_ + NT_) * ASTRIDE;

    extern __shared__ char smem[];
    uint32_t sb = smem_u32(smem);
    int tid = threadIdx.x, wid = tid >> 5, lane = tid & 31;
    int warp_m = wid % WGM, warp_n = wid / WGM;
    int b = blockIdx.z, e = g_expert[b];
    int m0 = blockIdx.y * MT_, n0 = blockIdx.x * NT_;

    const __half* Ab = A  + (size_t)b * Tn * K + (size_t)m0 * K;
    const __half* Bb = Bt + (size_t)e * Ntot * K + (size_t)n0 * K;

    const int nc = K / KC;

    float acc[4][2 * NJP][4];
    #pragma unroll
    for (int i = 0; i < 4; i++)
        #pragma unroll
        for (int j = 0; j < 2 * NJP; j++)
            #pragma unroll
            for (int q = 0; q < 4; q++) acc[i][j][q] = 0.f;

    // prologue: 3 chunks in flight
    load_chunk2<MT_, NT_, THREADS>(sb,              Ab, Bb, K, 0,      tid); CP_COMMIT();
    load_chunk2<MT_, NT_, THREADS>(sb + STAGE_,     Ab, Bb, K, KC,     tid); CP_COMMIT();
    load_chunk2<MT_, NT_, THREADS>(sb + 2 * STAGE_, Ab, Bb, K, 2 * KC, tid); CP_COMMIT();

    uint32_t lm_row = (lane & 15), lm_half = (lane >> 4) << 4;
    uint32_t aoff = lm_row * ASTRIDE + lm_half + (warp_m * 64) * ASTRIDE;
    uint32_t boff = MT_ * ASTRIDE + lm_row * ASTRIDE + lm_half + (warp_n * WCOLS) * ASTRIDE;

    for (int i = 0; i < nc; i++) {
        if (i < nc - 2)       CP_WAIT2();          // chunk i landed
        else if (i == nc - 2) CP_WAIT1();
        else                  CP_WAIT0();
        __syncthreads();                           // chunk i visible to all;
                                                   // all warps past compute(i-1)
        if (i + 3 < nc) {
            load_chunk2<MT_, NT_, THREADS>(sb + ((i + 3) % NSTAGE) * STAGE_,
                                           Ab, Bb, K, (i + 3) * KC, tid);
            CP_COMMIT();
        }

        uint32_t stg = sb + (i % NSTAGE) * STAGE_;
        #pragma unroll
        for (int ks = 0; ks < 2; ks++) {
            uint32_t a[4][4], bq[NJP][4];
            #pragma unroll
            for (int jp = 0; jp < NJP; jp++)
                ldmx4(bq[jp], stg + boff + jp * 16 * ASTRIDE + ks * 32);
            #pragma unroll
            for (int ia = 0; ia < 4; ia++)
                ldmx4(a[ia], stg + aoff + ia * 16 * ASTRIDE + ks * 32);
            #pragma unroll
            for (int ia = 0; ia < 4; ia++)
                #pragma unroll
                for (int j = 0; j < 2 * NJP; j++) {
                    int jp = j >> 1, hi = j & 1;
                    mma16816f(acc[ia][j], a[ia], bq[jp][hi], bq[jp][hi + 2]);
                }
        }
    }

    // ------------- epilogue -------------
    int mrow = m0 + warp_m * 64 + (lane >> 2);
    int ncol = n0 + warp_n * WCOLS + (lane & 3) * 2;
    const float* bb = bias + (size_t)e * Ntot;

    #pragma unroll
    for (int ia = 0; ia < 4; ia++) {
        #pragma unroll
        for (int j = 0; j < 2 * NJP; j++) {
            int n = ncol + j * 8;
            float2 b2 = *(const float2*)(bb + n);
            #pragma unroll
            for (int half = 0; half < 2; half++) {
                int m = mrow + ia * 16 + half * 8;
                float v0 = acc[ia][j][2 * half]     + b2.x;
                float v1 = acc[ia][j][2 * half + 1] + b2.y;
                if (FUSE1) {
                    v0 = fmaxf(v0, 0.f); v1 = fmaxf(v1, 0.f);
                    *(__half2*)(out_h + ((size_t)b * Tn + m) * Ntot + n) =
                        __floats2half2_rn(v0, v1);
                } else {
                    float2 o = make_float2(v0, v1);
                    *(float2*)(out_f + ((size_t)b * Tn + m) * Ntot + n) = o;
                }
            }
        }
    }
}

// ---------------------------------------------------------------------------
extern "C" void kernel_launch(void* const* d_in, const int* in_sizes, int n_in,
                              void* d_out, int out_size)
{
    const float* x  = (const float*)d_in[0];
    const float* Wp = (const float*)d_in[1];
    const float* bp = (const float*)d_in[2];
    const float* W1 = (const float*)d_in[3];
    const float* b1 = (const float*)d_in[4];
    const float* W2 = (const float*)d_in[5];
    const float* b2 = (const float*)d_in[6];

    float* out   = (float*)d_out;
    float* probs = out + (size_t)Bsz * Tn * Dn;
    float* idx   = probs + (size_t)Bsz * En;

    __half *x16, *w1t, *w2t, *h16;
    cudaGetSymbolAddress((void**)&x16, g_x16);
    cudaGetSymbolAddress((void**)&w1t, g_w1t);
    cudaGetSymbolAddress((void**)&w2t, g_w2t);
    cudaGetSymbolAddress((void**)&h16, g_h16);

    // GEMM1: 128x256, 512 thr (16 warps 2x8, warp 64x32), 1 CTA/SM, 4 stages.
    // GEMM2: 64x128, 256 thr (8 warps 1x8, warp 64x16), 2 CTA/SM, 4 stages.
    constexpr int SMEM1 = NSTAGE * (128 + 256) * ASTRIDE;   // 122880
    constexpr int SMEM2 = NSTAGE * (64 + 128) * ASTRIDE;    // 61440
    cudaFuncSetAttribute((const void*)mma_gemm<128, 256, 2, 512, 1, true>,
                         cudaFuncAttributeMaxDynamicSharedMemorySize, SMEM1);
    cudaFuncSetAttribute((const void*)mma_gemm<64, 128, 1, 256, 2, false>,
                         cudaFuncAttributeMaxDynamicSharedMemorySize, SMEM2);

    convert_x_pool<<<dim3(Bsz, 8), 256>>>(x);
    router_finish<<<Bsz, 256>>>(Wp, bp, probs, idx);
    transpose_all<<<dim3(Hn / 32, Dn / 32, 2 * En), 256>>>(W1, W2);

    // GEMM1: h = relu(x @ W1[e] + b1[e]),  K=D, Ntot=H  -> 1024 CTAs
    mma_gemm<128, 256, 2, 512, 1, true><<<dim3(Hn / 256, Tn / 128, Bsz), 512, SMEM1>>>(
        x16, w1t, b1, h16, nullptr, Dn, Hn);
    // GEMM2: out = h @ W2[e] + b2[e],      K=H, Ntot=D  -> 1024 CTAs, 2/SM
    mma_gemm<64, 128, 1, 256, 2, false><<<dim3(Dn / 128, Tn / 64, Bsz), 256, SMEM2>>>(
        h16, w2t, b2, nullptr, out, Hn, Dn);
}

// round 15
// speedup vs baseline: 7.9070x; 1.0726x over previous
#include <cuda_runtime.h>
#include <cuda_fp16.h>
#include <cstdint>
#include <math.h>

#define Bsz 32
#define Tn  512
#define Dn  512
#define En  8
#define Hn  2048

// ---------------- device scratch (static: allocation-guard safe) ----------
__device__ __align__(16) __half g_x16[(size_t)Bsz*Tn*Dn];
__device__ __align__(16) __half g_w1t[(size_t)En*Hn*Dn];   // [E][H][D] (N-major) fp16
__device__ __align__(16) __half g_w2t[(size_t)En*Dn*Hn];   // [E][D][H] (N-major) fp16
__device__ __align__(16) __half g_h16[(size_t)Bsz*Tn*Hn];
__device__ float g_pool[Bsz][8][Dn];
__device__ int   g_expert[Bsz];

// ---------------- small PTX helpers ---------------------------------------
__device__ __forceinline__ uint32_t smem_u32(const void* p) {
    uint32_t a;
    asm("{ .reg .u64 t; cvta.to.shared.u64 t, %1; cvt.u32.u64 %0, t; }" : "=r"(a) : "l"(p));
    return a;
}
__device__ __forceinline__ void cp16(uint32_t dst, const void* src) {
    asm volatile("cp.async.cg.shared.global [%0], [%1], 16;" :: "r"(dst), "l"(__cvta_generic_to_global(src)));
}
#define CP_COMMIT()  asm volatile("cp.async.commit_group;" ::: "memory")
#define CP_WAIT0()   asm volatile("cp.async.wait_group 0;" ::: "memory")
#define CP_WAIT1()   asm volatile("cp.async.wait_group 1;" ::: "memory")

__device__ __forceinline__ void ldmx4(uint32_t* r, uint32_t addr) {
    asm volatile("ldmatrix.sync.aligned.m8n8.x4.shared.b16 {%0,%1,%2,%3}, [%4];"
                 : "=r"(r[0]), "=r"(r[1]), "=r"(r[2]), "=r"(r[3]) : "r"(addr));
}
__device__ __forceinline__ void mma16816f(float* c, const uint32_t* a, uint32_t b0, uint32_t b1) {
    asm volatile("mma.sync.aligned.m16n8k16.row.col.f32.f16.f16.f32 "
                 "{%0,%1,%2,%3}, {%4,%5,%6,%7}, {%8,%9}, {%0,%1,%2,%3};"
                 : "+f"(c[0]), "+f"(c[1]), "+f"(c[2]), "+f"(c[3])
                 : "r"(a[0]), "r"(a[1]), "r"(a[2]), "r"(a[3]), "r"(b0), "r"(b1));
}

// ---------------- pre-pass: x -> fp16 + pooled partials -------------------
__global__ __launch_bounds__(256) void convert_x_pool(const float* __restrict__ x) {
    int b = blockIdx.x, sl = blockIdx.y;
    const float* xb = x + (size_t)b * Tn * Dn + (size_t)sl * 64 * Dn;
    __half* oh = g_x16 + (size_t)b * Tn * Dn + (size_t)sl * 64 * Dn;
    int t = threadIdx.x;
    float a0 = 0.f, a1 = 0.f;
    for (int r = 0; r < 64; r++) {
        float2 v = ((const float2*)(xb + (size_t)r * Dn))[t];
        ((__half2*)(oh + (size_t)r * Dn))[t] = __floats2half2_rn(v.x, v.y);
        a0 += v.x; a1 += v.y;
    }
    g_pool[b][sl][2 * t]     = a0;
    g_pool[b][sl][2 * t + 1] = a1;
}

// ---------------- router finish: logits, softmax, argmax ------------------
__global__ __launch_bounds__(256) void router_finish(
    const float* __restrict__ Wp, const float* __restrict__ bp,
    float* __restrict__ probs_out, float* __restrict__ idx_out)
{
    int b = blockIdx.x;
    __shared__ float pooled[Dn];
    __shared__ float logits[En];
    for (int d = threadIdx.x; d < Dn; d += 256) {
        float s = 0.f;
        #pragma unroll
        for (int sl = 0; sl < 8; sl++) s += g_pool[b][sl][d];
        pooled[d] = s * (1.0f / (float)Tn);
    }
    __syncthreads();
    int w = threadIdx.x >> 5, lane = threadIdx.x & 31;
    if (w < En) {
        float s = 0.f;
        for (int d = lane; d < Dn; d += 32) s += pooled[d] * Wp[(size_t)d * En + w];
        #pragma unroll
        for (int o = 16; o > 0; o >>= 1) s += __shfl_xor_sync(0xffffffffu, s, o);
        if (lane == 0) logits[w] = s + bp[w];
    }
    __syncthreads();
    if (threadIdx.x == 0) {
        float m = logits[0]; int am = 0;
        #pragma unroll
        for (int e = 1; e < En; e++) if (logits[e] > m) { m = logits[e]; am = e; }
        float ex[En], den = 0.f;
        #pragma unroll
        for (int e = 0; e < En; e++) { ex[e] = expf(logits[e] - m); den += ex[e]; }
        float inv = 1.0f / den;
        #pragma unroll
        for (int e = 0; e < En; e++) probs_out[b * En + e] = ex[e] * inv;
        idx_out[b]  = (float)am;
        g_expert[b] = am;
    }
}

// ---------------- pre-pass: transpose W1 and W2 to fp16 (one launch) ------
__global__ __launch_bounds__(256) void transpose_all(
    const float* __restrict__ W1, const float* __restrict__ W2)
{
    __shared__ float tile[32][33];
    bool isW1 = blockIdx.z < En;
    int e = isW1 ? blockIdx.z : blockIdx.z - En;
    int R = isW1 ? Dn : Hn;
    int C = isW1 ? Hn : Dn;
    int c0 = (isW1 ? blockIdx.x : blockIdx.y) * 32;
    int r0 = (isW1 ? blockIdx.y : blockIdx.x) * 32;
    const float* in = (isW1 ? W1 : W2) + (size_t)e * R * C;
    __half* oh = (isW1 ? g_w1t : g_w2t);
    int tx = threadIdx.x & 31, ty = threadIdx.x >> 5;
    #pragma unroll
    for (int i = 0; i < 32; i += 8)
        tile[ty + i][tx] = in[(size_t)(r0 + ty + i) * C + (c0 + tx)];
    __syncthreads();
    size_t ob = (size_t)e * R * C;
    #pragma unroll
    for (int i = 0; i < 32; i += 8) {
        int oc = c0 + ty + i;
        oh[ob + (size_t)oc * R + r0 + tx] = __float2half_rn(tile[tx][ty + i]);
    }
}

// ---------------- HMMA GEMM (single-term fp16, KC=64) -----------------------
// C[b](M, Ntot) = act(A[b](M,K) @ Bt[e](Ntot,K)^T + bias[e])
// A, B fp16; fp32 accumulate. 3-stage cp.async, 1 sync per 64-wide k-chunk.
#define KC 64
#define ASTRIDE 144                   // bytes per smem row (64 fp16 + 16B pad)
#define NSTAGE 3

template <int MT_, int NT_, int THREADS>
__device__ __forceinline__ void load_chunk2(
    uint32_t stageBase, const __half* __restrict__ A,
    const __half* __restrict__ Bt, int K, int k0, int tid)
{
    constexpr int ASEGS = MT_ * 8;          // 16B segments per A tile (64 fp16/row)
    #pragma unroll
    for (int idx = tid; idx < ASEGS; idx += THREADS) {
        int r = idx >> 3, seg = idx & 7;
        cp16(stageBase + r * ASTRIDE + seg * 16, A + (size_t)r * K + k0 + seg * 8);
    }
    constexpr int BSEGS = NT_ * 8;
    uint32_t bbase = stageBase + MT_ * ASTRIDE;
    #pragma unroll
    for (int idx = tid; idx < BSEGS; idx += THREADS) {
        int r = idx >> 3, seg = idx & 7;
        cp16(bbase + r * ASTRIDE + seg * 16, Bt + (size_t)r * K + k0 + seg * 8);
    }
}

template <int MT_, int NT_, int WGM, int THREADS, int MINCTA, bool FUSE1>
__global__ __launch_bounds__(THREADS, MINCTA) void mma_gemm(
    const __half* __restrict__ A, const __half* __restrict__ Bt,
    const float* __restrict__ bias,
    __half* __restrict__ out_h, float* __restrict__ out_f, int K, int Ntot)
{
    constexpr int NWARPS = THREADS / 32;
    constexpr int WGN    = NWARPS / WGM;
    constexpr int WCOLS  = NT_ / WGN;       // cols per warp
    constexpr int NJP    = WCOLS / 16;      // b ldmatrix.x4 per ks
    constexpr int STAGE_ = (MT_ + NT_) * ASTRIDE;

    extern __shared__ char smem[];
    uint32_t sb = smem_u32(smem);
    int tid = threadIdx.x, wid = tid >> 5, lane = tid & 31;
    int warp_m = wid % WGM, warp_n = wid / WGM;
    int b = blockIdx.z, e = g_expert[b];
    int m0 = blockIdx.y * MT_, n0 = blockIdx.x * NT_;

    const __half* Ab = A  + (size_t)b * Tn * K + (size_t)m0 * K;
    const __half* Bb = Bt + (size_t)e * Ntot * K + (size_t)n0 * K;

    const int nc = K / KC;

    float acc[4][2 * NJP][4];
    #pragma unroll
    for (int i = 0; i < 4; i++)
        #pragma unroll
        for (int j = 0; j < 2 * NJP; j++)
            #pragma unroll
            for (int q = 0; q < 4; q++) acc[i][j][q] = 0.f;

    // prologue: 2 chunks in flight
    load_chunk2<MT_, NT_, THREADS>(sb,          Ab, Bb, K, 0,  tid); CP_COMMIT();
    load_chunk2<MT_, NT_, THREADS>(sb + STAGE_, Ab, Bb, K, KC, tid); CP_COMMIT();

    uint32_t lm_row = (lane & 15), lm_half = (lane >> 4) << 4;
    uint32_t aoff = lm_row * ASTRIDE + lm_half + (warp_m * 64) * ASTRIDE;
    uint32_t boff = MT_ * ASTRIDE + lm_row * ASTRIDE + lm_half + (warp_n * WCOLS) * ASTRIDE;

    for (int i = 0; i < nc; i++) {
        if (i < nc - 1) CP_WAIT1(); else CP_WAIT0();   // chunk i landed
        __syncthreads();                               // chunk i visible to all;
                                                       // all warps past compute(i-1)
        if (i + 2 < nc) {
            load_chunk2<MT_, NT_, THREADS>(sb + ((i + 2) % NSTAGE) * STAGE_,
                                           Ab, Bb, K, (i + 2) * KC, tid);
            CP_COMMIT();
        }

        uint32_t stg = sb + (i % NSTAGE) * STAGE_;
        #pragma unroll
        for (int ks = 0; ks < 4; ks++) {               // 4 k-slices of 16
            uint32_t a[4][4], bq[NJP][4];
            #pragma unroll
            for (int jp = 0; jp < NJP; jp++)
                ldmx4(bq[jp], stg + boff + jp * 16 * ASTRIDE + ks * 32);
            #pragma unroll
            for (int ia = 0; ia < 4; ia++)
                ldmx4(a[ia], stg + aoff + ia * 16 * ASTRIDE + ks * 32);
            #pragma unroll
            for (int ia = 0; ia < 4; ia++)
                #pragma unroll
                for (int j = 0; j < 2 * NJP; j++) {
                    int jp = j >> 1, hi = j & 1;
                    mma16816f(acc[ia][j], a[ia], bq[jp][hi], bq[jp][hi + 2]);
                }
        }
    }

    // ------------- epilogue -------------
    int mrow = m0 + warp_m * 64 + (lane >> 2);
    int ncol = n0 + warp_n * WCOLS + (lane & 3) * 2;
    const float* bb = bias + (size_t)e * Ntot;

    #pragma unroll
    for (int ia = 0; ia < 4; ia++) {
        #pragma unroll
        for (int j = 0; j < 2 * NJP; j++) {
            int n = ncol + j * 8;
            float2 b2 = *(const float2*)(bb + n);
            #pragma unroll
            for (int half = 0; half < 2; half++) {
                int m = mrow + ia * 16 + half * 8;
                float v0 = acc[ia][j][2 * half]     + b2.x;
                float v1 = acc[ia][j][2 * half + 1] + b2.y;
                if (FUSE1) {
                    v0 = fmaxf(v0, 0.f); v1 = fmaxf(v1, 0.f);
                    *(__half2*)(out_h + ((size_t)b * Tn + m) * Ntot + n) =
                        __floats2half2_rn(v0, v1);
                } else {
                    float2 o = make_float2(v0, v1);
                    *(float2*)(out_f + ((size_t)b * Tn + m) * Ntot + n) = o;
                }
            }
        }
    }
}

// ---------------------------------------------------------------------------
extern "C" void kernel_launch(void* const* d_in, const int* in_sizes, int n_in,
                              void* d_out, int out_size)
{
    const float* x  = (const float*)d_in[0];
    const float* Wp = (const float*)d_in[1];
    const float* bp = (const float*)d_in[2];
    const float* W1 = (const float*)d_in[3];
    const float* b1 = (const float*)d_in[4];
    const float* W2 = (const float*)d_in[5];
    const float* b2 = (const float*)d_in[6];

    float* out   = (float*)d_out;
    float* probs = out + (size_t)Bsz * Tn * Dn;
    float* idx   = probs + (size_t)Bsz * En;

    __half *x16, *w1t, *w2t, *h16;
    cudaGetSymbolAddress((void**)&x16, g_x16);
    cudaGetSymbolAddress((void**)&w1t, g_w1t);
    cudaGetSymbolAddress((void**)&w2t, g_w2t);
    cudaGetSymbolAddress((void**)&h16, g_h16);

    // GEMM1: 128x256, 512 thr (16 warps 2x8, warp 64x32), 1 CTA/SM, 3 stages.
    // GEMM2: 128x128, 256 thr (8 warps 2x4, warp 64x32),  2 CTA/SM, 3 stages.
    constexpr int SMEM1 = NSTAGE * (128 + 256) * ASTRIDE;   // 165888
    constexpr int SMEM2 = NSTAGE * (128 + 128) * ASTRIDE;   // 110592
    cudaFuncSetAttribute((const void*)mma_gemm<128, 256, 2, 512, 1, true>,
                         cudaFuncAttributeMaxDynamicSharedMemorySize, SMEM1);
    cudaFuncSetAttribute((const void*)mma_gemm<128, 128, 2, 256, 2, false>,
                         cudaFuncAttributeMaxDynamicSharedMemorySize, SMEM2);

    convert_x_pool<<<dim3(Bsz, 8), 256>>>(x);
    router_finish<<<Bsz, 256>>>(Wp, bp, probs, idx);
    transpose_all<<<dim3(Hn / 32, Dn / 32, 2 * En), 256>>>(W1, W2);

    // GEMM1: h = relu(x @ W1[e] + b1[e]),  K=D, Ntot=H  -> 1024 CTAs
    mma_gemm<128, 256, 2, 512, 1, true><<<dim3(Hn / 256, Tn / 128, Bsz), 512, SMEM1>>>(
        x16, w1t, b1, h16, nullptr, Dn, Hn);
    // GEMM2: out = h @ W2[e] + b2[e],      K=H, Ntot=D  -> 512 CTAs, 2/SM
    mma_gemm<128, 128, 2, 256, 2, false><<<dim3(Dn / 128, Tn / 128, Bsz), 256, SMEM2>>>(
        h16, w2t, b2, nullptr, out, Hn, Dn);
}